// round 6
// baseline (speedup 1.0000x reference)
#include <cuda_runtime.h>
#include <cuda_bf16.h>
#include <math.h>
#include <stdint.h>

#define NB 512
#define NL 128
#define ND 512

// ---------------- scratch (static device globals) ----------------
__device__ float g_C[(size_t)NB * NL * ND];   // 134 MB
__device__ float g_Mt[ND * ND];               // att_mat transposed
__device__ float g_inv_na[NB], g_inv_nb[NB];
__device__ float g_rowm[NB * NL], g_colm[NB * NL];
__device__ float g_rows[NB * NL], g_cols[NB * NL];

// ---------------- helpers ----------------
__device__ __forceinline__ uint32_t smem_u32(const void* p) {
    uint32_t a;
    asm("{ .reg .u64 t; cvta.to.shared.u64 t, %1; cvt.u32.u64 %0, t; }" : "=r"(a) : "l"(p));
    return a;
}
__device__ __forceinline__ uint32_t swz(uint32_t o) { return o ^ ((o >> 3) & 0x70); }

__device__ __forceinline__ void ldm_x4(uint32_t* r, uint32_t addr) {
    asm volatile("ldmatrix.sync.aligned.m8n8.x4.shared.b16 {%0,%1,%2,%3}, [%4];"
        : "=r"(r[0]), "=r"(r[1]), "=r"(r[2]), "=r"(r[3]) : "r"(addr));
}
__device__ __forceinline__ void mma_bf16(float* c, const uint32_t* a, const uint32_t* b) {
    asm volatile("mma.sync.aligned.m16n8k16.row.col.f32.bf16.bf16.f32 "
        "{%0,%1,%2,%3}, {%4,%5,%6,%7}, {%8,%9}, {%0,%1,%2,%3};"
        : "+f"(c[0]), "+f"(c[1]), "+f"(c[2]), "+f"(c[3])
        : "r"(a[0]), "r"(a[1]), "r"(a[2]), "r"(a[3]), "r"(b[0]), "r"(b[1]));
}

// bf16 split: x ~= hi + lo
__device__ __forceinline__ void split2(float a, float b, uint32_t& h, uint32_t& l) {
    __nv_bfloat16 ha = __float2bfloat16_rn(a), hb = __float2bfloat16_rn(b);
    __nv_bfloat16 la = __float2bfloat16_rn(a - __bfloat162float(ha));
    __nv_bfloat16 lb = __float2bfloat16_rn(b - __bfloat162float(hb));
    h = ((uint32_t)__bfloat16_as_ushort(hb) << 16) | (uint32_t)__bfloat16_as_ushort(ha);
    l = ((uint32_t)__bfloat16_as_ushort(lb) << 16) | (uint32_t)__bfloat16_as_ushort(la);
}

__device__ __forceinline__ void ld8(float4* v, const float* p) {
    #pragma unroll
    for (int i = 0; i < 8; i++) v[i] = ((const float4*)p)[i];
}

// split 32 floats (one row segment) into bf16 hi/lo tiles with SW128 swizzle
__device__ __forceinline__ void st_split(char* dst_h, char* dst_l, int row, int cb,
                                         const float4* v) {
    uint32_t h[16], l[16];
    #pragma unroll
    for (int i = 0; i < 8; i++) {
        split2(v[i].x, v[i].y, h[2 * i], l[2 * i]);
        split2(v[i].z, v[i].w, h[2 * i + 1], l[2 * i + 1]);
    }
    #pragma unroll
    for (int g = 0; g < 4; g++) {
        uint32_t off = swz((uint32_t)(row * 128 + (cb + g * 8) * 2));
        *(uint4*)(dst_h + off) = make_uint4(h[4*g], h[4*g+1], h[4*g+2], h[4*g+3]);
        *(uint4*)(dst_l + off) = make_uint4(l[4*g], l[4*g+1], l[4*g+2], l[4*g+3]);
    }
}

// One K=64 chunk of the 3-product bf16-split MMA. Stage layout:
//   Ah @ +0, Al @ +16K, Bh @ +32K, Bl @ +48K; 128 rows x 64 bf16 (128B) each.
__device__ __forceinline__ void compute_chunk(uint32_t st, int lane, int m_base,
                                              int n_base, float acc[2][8][4]) {
    const int lrow = lane & 7, lmat = lane >> 3;
    const uint32_t a_row = (uint32_t)(m_base + (lmat & 1) * 8 + lrow) * 128;
    const uint32_t a_kb  = (uint32_t)((lmat >> 1) * 8) * 2;
    const uint32_t b_row = (uint32_t)(n_base + (lmat >> 1) * 8 + lrow) * 128;
    const uint32_t b_kb  = (uint32_t)((lmat & 1) * 8) * 2;
    #pragma unroll
    for (int ks = 0; ks < 4; ks++) {
        uint32_t Ah[2][4], Al[2][4];
        #pragma unroll
        for (int i = 0; i < 2; i++) {
            uint32_t off = swz(a_row + (uint32_t)i * 2048 + a_kb + ks * 32);
            ldm_x4(Ah[i], st + off);
            ldm_x4(Al[i], st + 16384 + off);
        }
        #pragma unroll
        for (int j = 0; j < 4; j++) {
            uint32_t off = swz(b_row + (uint32_t)j * 2048 + b_kb + ks * 32);
            uint32_t Bh[4], Bl[4];
            ldm_x4(Bh, st + 32768 + off);
            ldm_x4(Bl, st + 49152 + off);
            #pragma unroll
            for (int i = 0; i < 2; i++) {
                mma_bf16(acc[i][2*j],   Ah[i], &Bh[0]);
                mma_bf16(acc[i][2*j+1], Ah[i], &Bh[2]);
                mma_bf16(acc[i][2*j],   Ah[i], &Bl[0]);
                mma_bf16(acc[i][2*j+1], Ah[i], &Bl[2]);
                mma_bf16(acc[i][2*j],   Al[i], &Bh[0]);
                mma_bf16(acc[i][2*j+1], Al[i], &Bh[2]);
            }
        }
    }
}

#define ST_BYTES 65536
#define G_SMEM (3 * ST_BYTES + 1024)

// ---------------------------------------------------------------------------
// Kernel 0: transpose att_mat -> g_Mt[n][k] = M[k][n]
// ---------------------------------------------------------------------------
__global__ __launch_bounds__(256) void transpose_kernel(const float* __restrict__ M) {
    __shared__ float t[32][33];
    const int bx = blockIdx.x, by = blockIdx.y;
    const int tx = threadIdx.x, ty = threadIdx.y;
    int x = bx * 32 + tx;
    #pragma unroll
    for (int j = 0; j < 32; j += 8)
        t[ty + j][tx] = M[(by * 32 + ty + j) * ND + x];
    __syncthreads();
    x = by * 32 + tx;
    #pragma unroll
    for (int j = 0; j < 32; j += 8)
        g_Mt[(size_t)(bx * 32 + ty + j) * ND + x] = t[tx][ty + j];
}

// ---------------------------------------------------------------------------
// Kernel 1: per-batch Frobenius norms
// ---------------------------------------------------------------------------
__global__ __launch_bounds__(256) void norms_kernel(
    const int* __restrict__ t1c, const int* __restrict__ t2c,
    const float* __restrict__ E)
{
    const int b = blockIdx.x, tid = threadIdx.x;
    float s1 = 0.f, s2 = 0.f;
    for (int l = 0; l < NL; l++) {
        const float* r1 = E + (size_t)t1c[b * NL + l] * ND;
        const float* r2 = E + (size_t)t2c[b * NL + l] * ND;
        float a0 = r1[tid], a1 = r1[tid + 256];
        s1 += a0 * a0 + a1 * a1;
        float c0 = r2[tid], c1 = r2[tid + 256];
        s2 += c0 * c0 + c1 * c1;
    }
    __shared__ float sh1[8], sh2[8];
    #pragma unroll
    for (int o = 16; o; o >>= 1) {
        s1 += __shfl_xor_sync(0xffffffffu, s1, o);
        s2 += __shfl_xor_sync(0xffffffffu, s2, o);
    }
    if ((tid & 31) == 0) { sh1[tid >> 5] = s1; sh2[tid >> 5] = s2; }
    __syncthreads();
    if (tid < 8) {
        s1 = sh1[tid]; s2 = sh2[tid];
        #pragma unroll
        for (int o = 4; o; o >>= 1) {
            s1 += __shfl_xor_sync(0xffu, s1, o);
            s2 += __shfl_xor_sync(0xffu, s2, o);
        }
        if (tid == 0) { g_inv_na[b] = rsqrtf(s1); g_inv_nb[b] = rsqrtf(s2); }
    }
}

// ---------------------------------------------------------------------------
// Kernel 2: GEMM1 — C = gather(E, t1c) @ M  (via Mt, mma.sync bf16-split)
// ---------------------------------------------------------------------------
__global__ __launch_bounds__(256, 1) void gemm1_kernel(
    const int* __restrict__ idx, const float* __restrict__ E)
{
    extern __shared__ char smem_raw[];
    const uint32_t sb_raw = smem_u32(smem_raw);
    const uint32_t pad = ((sb_raw + 1023) & ~1023u) - sb_raw;
    char* smem = smem_raw + pad;
    const uint32_t sb = sb_raw + pad;

    const int tid = threadIdx.x;
    const int m0 = blockIdx.y * 128, n0 = blockIdx.x * 128;
    const int lr = tid >> 1, cb = (tid & 1) * 32;
    const float* aptr = E + (size_t)idx[m0 + lr] * ND + cb;
    const float* bptr = g_Mt + (size_t)(n0 + lr) * ND + cb;

    float acc[2][8][4];
    #pragma unroll
    for (int i = 0; i < 2; i++)
        #pragma unroll
        for (int j = 0; j < 8; j++)
            #pragma unroll
            for (int q = 0; q < 4; q++) acc[i][j][q] = 0.f;

    float4 va[8], vb[8];
    // prologue: chunks 0, 1
    ld8(va, aptr);      ld8(vb, bptr);
    st_split(smem, smem + 16384, lr, cb, va);
    st_split(smem + 32768, smem + 49152, lr, cb, vb);
    ld8(va, aptr + 64); ld8(vb, bptr + 64);
    st_split(smem + ST_BYTES, smem + ST_BYTES + 16384, lr, cb, va);
    st_split(smem + ST_BYTES + 32768, smem + ST_BYTES + 49152, lr, cb, vb);
    __syncthreads();

    const int wid = tid >> 5, lane = tid & 31;
    const int m_base = (wid >> 1) * 32, n_base = (wid & 1) * 64;

    for (int c = 0; c < 8; c++) {
        if (c + 2 < 8) { ld8(va, aptr + (c + 2) * 64); ld8(vb, bptr + (c + 2) * 64); }
        compute_chunk(sb + (c % 3) * ST_BYTES, lane, m_base, n_base, acc);
        if (c + 2 < 8) {
            char* stg = smem + ((c + 2) % 3) * ST_BYTES;
            st_split(stg, stg + 16384, lr, cb, va);
            st_split(stg + 32768, stg + 49152, lr, cb, vb);
        }
        __syncthreads();
    }

    #pragma unroll
    for (int i = 0; i < 2; i++) {
        int gr = m0 + m_base + i * 16 + (lane >> 2);
        #pragma unroll
        for (int j8 = 0; j8 < 8; j8++) {
            int gc = n0 + n_base + j8 * 8 + (lane & 3) * 2;
            float* p = g_C + (size_t)gr * ND + gc;
            *(float2*)p = make_float2(acc[i][j8][0], acc[i][j8][1]);
            *(float2*)(p + 8 * ND) = make_float2(acc[i][j8][2], acc[i][j8][3]);
        }
    }
}

// ---------------------------------------------------------------------------
// Kernel 3: GEMM2 — S[b] = tanh(scale_b * C[b] @ gather(E,t2c[b])^T)
//           fused tanh + S store + row/col means
// ---------------------------------------------------------------------------
__global__ __launch_bounds__(256, 1) void gemm2_kernel(
    const int* __restrict__ idx2, const float* __restrict__ E,
    float* __restrict__ outS)
{
    extern __shared__ char smem_raw[];
    const uint32_t sb_raw = smem_u32(smem_raw);
    const uint32_t pad = ((sb_raw + 1023) & ~1023u) - sb_raw;
    char* smem = smem_raw + pad;
    const uint32_t sb = sb_raw + pad;

    const int tid = threadIdx.x;
    const int b = blockIdx.x;
    const int lr = tid >> 1, cb = (tid & 1) * 32;
    const float* aptr = g_C + ((size_t)b * NL + lr) * ND + cb;
    const float* bptr = E + (size_t)idx2[b * NL + lr] * ND + cb;

    float acc[2][8][4];
    #pragma unroll
    for (int i = 0; i < 2; i++)
        #pragma unroll
        for (int j = 0; j < 8; j++)
            #pragma unroll
            for (int q = 0; q < 4; q++) acc[i][j][q] = 0.f;

    float4 va[8], vb[8];
    ld8(va, aptr);      ld8(vb, bptr);
    st_split(smem, smem + 16384, lr, cb, va);
    st_split(smem + 32768, smem + 49152, lr, cb, vb);
    ld8(va, aptr + 64); ld8(vb, bptr + 64);
    st_split(smem + ST_BYTES, smem + ST_BYTES + 16384, lr, cb, va);
    st_split(smem + ST_BYTES + 32768, smem + ST_BYTES + 49152, lr, cb, vb);
    __syncthreads();

    const int wid = tid >> 5, lane = tid & 31;
    const int m_base = (wid >> 1) * 32, n_base = (wid & 1) * 64;

    for (int c = 0; c < 8; c++) {
        if (c + 2 < 8) { ld8(va, aptr + (c + 2) * 64); ld8(vb, bptr + (c + 2) * 64); }
        compute_chunk(sb + (c % 3) * ST_BYTES, lane, m_base, n_base, acc);
        if (c + 2 < 8) {
            char* stg = smem + ((c + 2) % 3) * ST_BYTES;
            st_split(stg, stg + 16384, lr, cb, va);
            st_split(stg + 32768, stg + 49152, lr, cb, vb);
        }
        __syncthreads();
    }

    // epilogue: tanh + store + fused means (smem stages are dead now)
    float* rs = (float*)smem;
    float* cs = rs + 128;
    if (tid < 128) { rs[tid] = 0.f; cs[tid] = 0.f; }
    __syncthreads();

    const float scale = g_inv_na[b] * g_inv_nb[b];
    float* Sb = outS + (size_t)b * NL * NL;
    float cpart0[8], cpart1[8];
    #pragma unroll
    for (int j8 = 0; j8 < 8; j8++) { cpart0[j8] = 0.f; cpart1[j8] = 0.f; }
    float rpart[2][2];
    rpart[0][0] = rpart[0][1] = rpart[1][0] = rpart[1][1] = 0.f;

    #pragma unroll
    for (int i = 0; i < 2; i++) {
        int r0 = m_base + i * 16 + (lane >> 2);
        #pragma unroll
        for (int j8 = 0; j8 < 8; j8++) {
            int col = n_base + j8 * 8 + (lane & 3) * 2;
            float v0 = tanhf(acc[i][j8][0] * scale);
            float v1 = tanhf(acc[i][j8][1] * scale);
            float v2 = tanhf(acc[i][j8][2] * scale);
            float v3 = tanhf(acc[i][j8][3] * scale);
            float* p = Sb + (size_t)r0 * NL + col;
            *(float2*)p = make_float2(v0, v1);
            *(float2*)(p + 8 * NL) = make_float2(v2, v3);
            rpart[i][0] += v0 + v1;
            rpart[i][1] += v2 + v3;
            cpart0[j8] += v0 + v2;
            cpart1[j8] += v1 + v3;
        }
    }
    #pragma unroll
    for (int i = 0; i < 2; i++) {
        atomicAdd(&rs[m_base + i * 16 + (lane >> 2)], rpart[i][0]);
        atomicAdd(&rs[m_base + i * 16 + (lane >> 2) + 8], rpart[i][1]);
    }
    #pragma unroll
    for (int j8 = 0; j8 < 8; j8++) {
        atomicAdd(&cs[n_base + j8 * 8 + (lane & 3) * 2], cpart0[j8]);
        atomicAdd(&cs[n_base + j8 * 8 + (lane & 3) * 2 + 1], cpart1[j8]);
    }
    __syncthreads();
    if (tid < 128) {
        g_rowm[b * NL + tid] = rs[tid] * (1.0f / NL);
        g_colm[b * NL + tid] = cs[tid] * (1.0f / NL);
    }
}

// ---------------------------------------------------------------------------
// Kernel 4: softmax over precomputed means (tiny)
// ---------------------------------------------------------------------------
__global__ __launch_bounds__(128) void softmax_kernel()
{
    const int b = blockIdx.x, t = threadIdx.x;
    __shared__ float buf[128];
    float v = g_rowm[b * NL + t];
    buf[t] = v; __syncthreads();
    for (int s = 64; s; s >>= 1) { if (t < s) buf[t] = fmaxf(buf[t], buf[t + s]); __syncthreads(); }
    float mx = buf[0]; __syncthreads();
    float e = expf(v - mx);
    buf[t] = e; __syncthreads();
    for (int s = 64; s; s >>= 1) { if (t < s) buf[t] += buf[t + s]; __syncthreads(); }
    g_rows[b * NL + t] = e / buf[0];
    __syncthreads();
    v = g_colm[b * NL + t];
    buf[t] = v; __syncthreads();
    for (int s = 64; s; s >>= 1) { if (t < s) buf[t] = fmaxf(buf[t], buf[t + s]); __syncthreads(); }
    mx = buf[0]; __syncthreads();
    e = expf(v - mx);
    buf[t] = e; __syncthreads();
    for (int s = 64; s; s >>= 1) { if (t < s) buf[t] += buf[t + s]; __syncthreads(); }
    g_cols[b * NL + t] = e / buf[0];
}

// ---------------------------------------------------------------------------
// Kernel 5: weighted re-gather + logits
// ---------------------------------------------------------------------------
__global__ __launch_bounds__(256) void final_kernel(
    const int* __restrict__ t1c, const int* __restrict__ t2c,
    const float* __restrict__ E, const float* __restrict__ w,
    const float* __restrict__ bp, float* __restrict__ out)
{
    const int b = blockIdx.x, tid = threadIdx.x;
    __shared__ float rw[NL], cw[NL];
    if (tid < NL) { rw[tid] = g_rows[b * NL + tid]; cw[tid] = g_cols[b * NL + tid]; }
    __syncthreads();
    float nA0 = 0.f, nA1 = 0.f, nB0 = 0.f, nB1 = 0.f;
    for (int l = 0; l < NL; l++) {
        const float* r1 = E + (size_t)t1c[b * NL + l] * ND;
        const float* r2 = E + (size_t)t2c[b * NL + l] * ND;
        float wr = rw[l], wc = cw[l];
        nA0 += wr * r1[tid];  nA1 += wr * r1[tid + 256];
        nB0 += wc * r2[tid];  nB1 += wc * r2[tid + 256];
    }
    const float scale = g_inv_na[b] * g_inv_nb[b];
    float part = (nA0 * nB0 * w[tid] + nA1 * nB1 * w[tid + 256]) * scale;
    __shared__ float sh[8];
    #pragma unroll
    for (int o = 16; o; o >>= 1) part += __shfl_xor_sync(0xffffffffu, part, o);
    if ((tid & 31) == 0) sh[tid >> 5] = part;
    __syncthreads();
    if (tid < 8) {
        part = sh[tid];
        #pragma unroll
        for (int o = 4; o; o >>= 1) part += __shfl_xor_sync(0xffu, part, o);
        if (tid == 0) out[b] = part + bp[0];
    }
}

// ---------------------------------------------------------------------------
extern "C" void kernel_launch(void* const* d_in, const int* in_sizes, int n_in,
                              void* d_out, int out_size)
{
    (void)in_sizes; (void)n_in; (void)out_size;
    const int*   t1c = (const int*)d_in[2];
    const int*   t2c = (const int*)d_in[3];
    const float* E   = (const float*)d_in[4];
    const float* M   = (const float*)d_in[5];
    const float* w   = (const float*)d_in[6];
    const float* bp  = (const float*)d_in[7];
    float* out  = (float*)d_out;
    float* outS = out + NB;   // output = concat(logits[512], S[512*128*128])

    cudaFuncSetAttribute(gemm1_kernel, cudaFuncAttributeMaxDynamicSharedMemorySize, G_SMEM);
    cudaFuncSetAttribute(gemm2_kernel, cudaFuncAttributeMaxDynamicSharedMemorySize, G_SMEM);

    transpose_kernel<<<dim3(16, 16), dim3(32, 8)>>>(M);
    norms_kernel<<<NB, 256>>>(t1c, t2c, E);
    gemm1_kernel<<<dim3(4, 512), 256, G_SMEM>>>(t1c, E);
    gemm2_kernel<<<NB, 256, G_SMEM>>>(t2c, E, outS);
    softmax_kernel<<<NB, 128>>>();
    final_kernel<<<NB, 256>>>(t1c, t2c, E, w, bp, out);
}

// round 7
// speedup vs baseline: 2.3177x; 2.3177x over previous
#include <cuda_runtime.h>
#include <cuda_bf16.h>
#include <math.h>
#include <stdint.h>

#define NB 512
#define NL 128
#define ND 512
#define NROWS ((size_t)NB * NL)   // 65536

// ---------------- scratch (static device globals) ----------------
// packed 2x bf16 per uint32; row = 256 uint32 = 512 cols
__device__ uint32_t g_A1h[NROWS * 256], g_A1l[NROWS * 256];  // gather(E,t1) hi/lo
__device__ uint32_t g_B2h[NROWS * 256], g_B2l[NROWS * 256];  // gather(E,t2) hi/lo
__device__ uint32_t g_Ch [NROWS * 256], g_Cl [NROWS * 256];  // C = A1 @ M hi/lo
__device__ uint32_t g_Mth[ND * 256],    g_Mtl[ND * 256];     // Mt[n][k] hi/lo
__device__ float g_inv_na[NB], g_inv_nb[NB];
__device__ float g_rowm[NB * NL], g_colm[NB * NL];
__device__ float g_rows[NB * NL], g_cols[NB * NL];

// ---------------- helpers ----------------
__device__ __forceinline__ uint32_t smem_u32(const void* p) {
    uint32_t a;
    asm("{ .reg .u64 t; cvta.to.shared.u64 t, %1; cvt.u32.u64 %0, t; }" : "=r"(a) : "l"(p));
    return a;
}
__device__ __forceinline__ uint32_t swz(uint32_t o) { return o ^ ((o >> 3) & 0x70); }

#define CP16(dst, src) \
    asm volatile("cp.async.cg.shared.global [%0], [%1], 16;" :: "r"(dst), "l"(src))
#define CP_COMMIT() asm volatile("cp.async.commit_group;" ::: "memory")
#define CP_WAIT(n)  asm volatile("cp.async.wait_group %0;" :: "n"(n) : "memory")

__device__ __forceinline__ void ldm_x4(uint32_t* r, uint32_t addr) {
    asm volatile("ldmatrix.sync.aligned.m8n8.x4.shared.b16 {%0,%1,%2,%3}, [%4];"
        : "=r"(r[0]), "=r"(r[1]), "=r"(r[2]), "=r"(r[3]) : "r"(addr));
}
__device__ __forceinline__ void mma_bf16(float* c, const uint32_t* a, const uint32_t* b) {
    asm volatile("mma.sync.aligned.m16n8k16.row.col.f32.bf16.bf16.f32 "
        "{%0,%1,%2,%3}, {%4,%5,%6,%7}, {%8,%9}, {%0,%1,%2,%3};"
        : "+f"(c[0]), "+f"(c[1]), "+f"(c[2]), "+f"(c[3])
        : "r"(a[0]), "r"(a[1]), "r"(a[2]), "r"(a[3]), "r"(b[0]), "r"(b[1]));
}

// bf16 split: x ~= hi + lo, packed pairs
__device__ __forceinline__ void split2(float a, float b, uint32_t& h, uint32_t& l) {
    __nv_bfloat16 ha = __float2bfloat16_rn(a), hb = __float2bfloat16_rn(b);
    __nv_bfloat16 la = __float2bfloat16_rn(a - __bfloat162float(ha));
    __nv_bfloat16 lb = __float2bfloat16_rn(b - __bfloat162float(hb));
    h = ((uint32_t)__bfloat16_as_ushort(hb) << 16) | (uint32_t)__bfloat16_as_ushort(ha);
    l = ((uint32_t)__bfloat16_as_ushort(lb) << 16) | (uint32_t)__bfloat16_as_ushort(lb ? lb : lb);
    l = ((uint32_t)__bfloat16_as_ushort(lb) << 16) | (uint32_t)__bfloat16_as_ushort(la);
}
__device__ __forceinline__ float2 unsplit(uint32_t h, uint32_t l) {
    __nv_bfloat162 H = *reinterpret_cast<__nv_bfloat162*>(&h);
    __nv_bfloat162 L = *reinterpret_cast<__nv_bfloat162*>(&l);
    return make_float2(__bfloat162float(H.x) + __bfloat162float(L.x),
                       __bfloat162float(H.y) + __bfloat162float(L.y));
}

// One K=64 chunk. Stage layout: Ah @ 0, Al @ +16K, Bh @ +b_off, Bl @ +b_off+b_delta.
// 128B swizzled rows. Warp tile 32x64 -> acc[2][8][4]; 3 split products.
__device__ __forceinline__ void compute_chunk(uint32_t st, int lane, int m_base,
                                              int n_base, float acc[2][8][4],
                                              uint32_t b_off, uint32_t b_delta) {
    const int lrow = lane & 7, lmat = lane >> 3;
    const uint32_t a_row = (uint32_t)(m_base + (lmat & 1) * 8 + lrow) * 128;
    const uint32_t a_kb  = (uint32_t)((lmat >> 1) * 8) * 2;
    const uint32_t b_row = (uint32_t)(n_base + (lmat >> 1) * 8 + lrow) * 128;
    const uint32_t b_kb  = (uint32_t)((lmat & 1) * 8) * 2;
    #pragma unroll
    for (int ks = 0; ks < 4; ks++) {
        uint32_t Ah[2][4], Al[2][4];
        #pragma unroll
        for (int i = 0; i < 2; i++) {
            uint32_t off = swz(a_row + (uint32_t)i * 2048 + a_kb + ks * 32);
            ldm_x4(Ah[i], st + off);
            ldm_x4(Al[i], st + 16384 + off);
        }
        #pragma unroll
        for (int j = 0; j < 4; j++) {
            uint32_t off = swz(b_row + (uint32_t)j * 2048 + b_kb + ks * 32);
            uint32_t Bh[4], Bl[4];
            ldm_x4(Bh, st + b_off + off);
            ldm_x4(Bl, st + b_off + b_delta + off);
            #pragma unroll
            for (int i = 0; i < 2; i++) {
                mma_bf16(acc[i][2*j],   Ah[i], &Bh[0]);
                mma_bf16(acc[i][2*j+1], Ah[i], &Bh[2]);
                mma_bf16(acc[i][2*j],   Ah[i], &Bl[0]);
                mma_bf16(acc[i][2*j+1], Ah[i], &Bl[2]);
                mma_bf16(acc[i][2*j],   Al[i], &Bh[0]);
                mma_bf16(acc[i][2*j+1], Al[i], &Bh[2]);
            }
        }
    }
}

// ---------------------------------------------------------------------------
// Kernel 0: transpose + split att_mat -> g_Mth/g_Mtl (Mt[n][k] = M[k][n])
// ---------------------------------------------------------------------------
__global__ __launch_bounds__(256) void prep_mt_kernel(const float* __restrict__ M) {
    __shared__ float t[32][33];
    const int n0 = blockIdx.x * 32, k0 = blockIdx.y * 32;
    const int tid = threadIdx.x;
    const int tx = tid & 31, ty = tid >> 5;
    #pragma unroll
    for (int j = 0; j < 32; j += 8)
        t[ty + j][tx] = M[(size_t)(k0 + ty + j) * ND + n0 + tx];
    __syncthreads();
    #pragma unroll
    for (int rep = 0; rep < 2; rep++) {
        int idx = rep * 256 + tid;
        int nl = idx >> 4, kp = idx & 15;
        uint32_t h, l;
        split2(t[2 * kp][nl], t[2 * kp + 1][nl], h, l);
        size_t o = (size_t)(n0 + nl) * 256 + (k0 >> 1) + kp;
        g_Mth[o] = h;
        g_Mtl[o] = l;
    }
}

// ---------------------------------------------------------------------------
// Kernel 1: gather + split + norms (fused)
// ---------------------------------------------------------------------------
__global__ __launch_bounds__(256) void prep_kernel(
    const int* __restrict__ t1c, const int* __restrict__ t2c,
    const float* __restrict__ E)
{
    const int b = blockIdx.x, tid = threadIdx.x;
    __shared__ int i1s[NL], i2s[NL];
    if (tid < NL) { i1s[tid] = t1c[b * NL + tid]; i2s[tid] = t2c[b * NL + tid]; }
    __syncthreads();
    float s1 = 0.f, s2 = 0.f;
    for (int l = 0; l < NL; l++) {
        float2 v1 = ((const float2*)(E + (size_t)i1s[l] * ND))[tid];
        float2 v2 = ((const float2*)(E + (size_t)i2s[l] * ND))[tid];
        s1 += v1.x * v1.x + v1.y * v1.y;
        s2 += v2.x * v2.x + v2.y * v2.y;
        size_t o = (size_t)(b * NL + l) * 256 + tid;
        uint32_t h, lo;
        split2(v1.x, v1.y, h, lo); g_A1h[o] = h; g_A1l[o] = lo;
        split2(v2.x, v2.y, h, lo); g_B2h[o] = h; g_B2l[o] = lo;
    }
    __shared__ float sh1[8], sh2[8];
    #pragma unroll
    for (int o = 16; o; o >>= 1) {
        s1 += __shfl_xor_sync(0xffffffffu, s1, o);
        s2 += __shfl_xor_sync(0xffffffffu, s2, o);
    }
    if ((tid & 31) == 0) { sh1[tid >> 5] = s1; sh2[tid >> 5] = s2; }
    __syncthreads();
    if (tid < 8) {
        s1 = sh1[tid]; s2 = sh2[tid];
        #pragma unroll
        for (int o = 4; o; o >>= 1) {
            s1 += __shfl_xor_sync(0xffu, s1, o);
            s2 += __shfl_xor_sync(0xffu, s2, o);
        }
        if (tid == 0) { g_inv_na[b] = rsqrtf(s1); g_inv_nb[b] = rsqrtf(s2); }
    }
}

// ---------------------------------------------------------------------------
// Kernel 2: GEMM1 — C = A1 @ Mt^T, 128x256 block tile, 512 thr, cp.async 2-stage
//   stage: Ah 16K | Al 16K | Bh 32K | Bl 32K = 96KB
// ---------------------------------------------------------------------------
#define G1_STAGE 98304
#define G1_SMEM  (2 * G1_STAGE + 1024)

__global__ __launch_bounds__(512, 1) void gemm1_kernel()
{
    extern __shared__ char smem_raw[];
    const uint32_t sb_raw = smem_u32(smem_raw);
    const uint32_t sb = (sb_raw + 1023) & ~1023u;
    const int tid = threadIdx.x;
    const int m0 = blockIdx.y * 128, n0 = blockIdx.x * 256;

    const char* srcAh = (const char*)g_A1h + (size_t)m0 * 1024;
    const char* srcAl = (const char*)g_A1l + (size_t)m0 * 1024;
    const char* srcBh = (const char*)g_Mth + (size_t)n0 * 1024;
    const char* srcBl = (const char*)g_Mtl + (size_t)n0 * 1024;

    auto load_stage = [&](int c, int s) {
        const uint32_t stg = sb + s * G1_STAGE;
        #pragma unroll
        for (int q = 0; q < 2; q++) {     // A: 128 rows x 8 segs, hi+lo
            int sid = tid + q * 512;
            int r = sid >> 3, seg = sid & 7;
            uint32_t dst = stg + swz((uint32_t)(r * 128 + seg * 16));
            size_t so = (size_t)r * 1024 + c * 128 + seg * 16;
            CP16(dst, srcAh + so);
            CP16(dst + 16384, srcAl + so);
        }
        #pragma unroll
        for (int q = 0; q < 4; q++) {     // B: 256 rows x 8 segs, hi+lo
            int sid = tid + q * 512;
            int r = sid >> 3, seg = sid & 7;
            uint32_t dst = stg + 32768 + swz((uint32_t)(r * 128 + seg * 16));
            size_t so = (size_t)r * 1024 + c * 128 + seg * 16;
            CP16(dst, srcBh + so);
            CP16(dst + 32768, srcBl + so);
        }
    };

    float acc[2][8][4];
    #pragma unroll
    for (int i = 0; i < 2; i++)
        #pragma unroll
        for (int j = 0; j < 8; j++)
            #pragma unroll
            for (int q = 0; q < 4; q++) acc[i][j][q] = 0.f;

    load_stage(0, 0); CP_COMMIT();
    load_stage(1, 1); CP_COMMIT();
    CP_WAIT(1); __syncthreads();

    const int wid = tid >> 5, lane = tid & 31;
    const int m_base = (wid >> 2) * 32, n_base = (wid & 3) * 64;

    for (int c = 0; c < 8; c++) {
        compute_chunk(sb + (c & 1) * G1_STAGE, lane, m_base, n_base, acc, 32768, 32768);
        __syncthreads();
        if (c + 2 < 8) { load_stage(c + 2, c & 1); CP_COMMIT(); CP_WAIT(1); }
        else if (c == 6) { CP_WAIT(0); }
        __syncthreads();
    }

    // epilogue: split acc -> g_Ch / g_Cl
    #pragma unroll
    for (int i = 0; i < 2; i++) {
        int gr = m0 + m_base + i * 16 + (lane >> 2);
        #pragma unroll
        for (int j8 = 0; j8 < 8; j8++) {
            int gc = n0 + n_base + j8 * 8 + (lane & 3) * 2;
            size_t o0 = (size_t)gr * 256 + (gc >> 1);
            size_t o1 = (size_t)(gr + 8) * 256 + (gc >> 1);
            uint32_t h, l;
            split2(acc[i][j8][0], acc[i][j8][1], h, l);
            g_Ch[o0] = h; g_Cl[o0] = l;
            split2(acc[i][j8][2], acc[i][j8][3], h, l);
            g_Ch[o1] = h; g_Cl[o1] = l;
        }
    }
}

// ---------------------------------------------------------------------------
// Kernel 3: GEMM2 — S[b] = tanh(scale * C[b] @ B2[b]^T), fused means
//   stage: Ah 16K | Al 16K | Bh 16K | Bl 16K = 64KB, 3 stages
// ---------------------------------------------------------------------------
#define G2_STAGE 65536
#define G2_SMEM  (3 * G2_STAGE + 1024)

__global__ __launch_bounds__(256, 1) void gemm2_kernel(float* __restrict__ outS)
{
    extern __shared__ char smem_raw[];
    const uint32_t sb_raw = smem_u32(smem_raw);
    const uint32_t sb = (sb_raw + 1023) & ~1023u;
    char* smem = smem_raw + (sb - sb_raw);
    const int tid = threadIdx.x;
    const int b = blockIdx.x;

    const char* srcAh = (const char*)g_Ch  + (size_t)b * NL * 1024;
    const char* srcAl = (const char*)g_Cl  + (size_t)b * NL * 1024;
    const char* srcBh = (const char*)g_B2h + (size_t)b * NL * 1024;
    const char* srcBl = (const char*)g_B2l + (size_t)b * NL * 1024;

    auto load_stage = [&](int c, int s) {
        const uint32_t stg = sb + s * G2_STAGE;
        #pragma unroll
        for (int q = 0; q < 4; q++) {
            int sid = tid + q * 256;
            int r = sid >> 3, seg = sid & 7;
            uint32_t dst = stg + swz((uint32_t)(r * 128 + seg * 16));
            size_t so = (size_t)r * 1024 + c * 128 + seg * 16;
            CP16(dst, srcAh + so);
            CP16(dst + 16384, srcAl + so);
            CP16(dst + 32768, srcBh + so);
            CP16(dst + 49152, srcBl + so);
        }
    };

    float acc[2][8][4];
    #pragma unroll
    for (int i = 0; i < 2; i++)
        #pragma unroll
        for (int j = 0; j < 8; j++)
            #pragma unroll
            for (int q = 0; q < 4; q++) acc[i][j][q] = 0.f;

    load_stage(0, 0); CP_COMMIT();
    load_stage(1, 1); CP_COMMIT();
    load_stage(2, 2); CP_COMMIT();
    CP_WAIT(2); __syncthreads();

    const int wid = tid >> 5, lane = tid & 31;
    const int m_base = (wid >> 1) * 32, n_base = (wid & 1) * 64;

    for (int c = 0; c < 8; c++) {
        compute_chunk(sb + (c % 3) * G2_STAGE, lane, m_base, n_base, acc, 32768, 16384);
        __syncthreads();
        if (c + 3 < 8)      { load_stage(c + 3, c % 3); CP_COMMIT(); CP_WAIT(2); }
        else if (c == 5)    { CP_WAIT(1); }
        else if (c == 6)    { CP_WAIT(0); }
        __syncthreads();
    }

    // epilogue: tanh + S store + fused row/col means
    float* rs = (float*)smem;
    float* cs = rs + 128;
    if (tid < 128) { rs[tid] = 0.f; cs[tid] = 0.f; }
    __syncthreads();

    const float scale = g_inv_na[b] * g_inv_nb[b];
    float* Sb = outS + (size_t)b * NL * NL;
    float cpart0[8], cpart1[8];
    #pragma unroll
    for (int j8 = 0; j8 < 8; j8++) { cpart0[j8] = 0.f; cpart1[j8] = 0.f; }
    float rpart[2][2] = {{0.f, 0.f}, {0.f, 0.f}};

    #pragma unroll
    for (int i = 0; i < 2; i++) {
        int r0 = m_base + i * 16 + (lane >> 2);
        #pragma unroll
        for (int j8 = 0; j8 < 8; j8++) {
            int col = n_base + j8 * 8 + (lane & 3) * 2;
            float v0 = tanhf(acc[i][j8][0] * scale);
            float v1 = tanhf(acc[i][j8][1] * scale);
            float v2 = tanhf(acc[i][j8][2] * scale);
            float v3 = tanhf(acc[i][j8][3] * scale);
            float* p = Sb + (size_t)r0 * NL + col;
            *(float2*)p = make_float2(v0, v1);
            *(float2*)(p + 8 * NL) = make_float2(v2, v3);
            rpart[i][0] += v0 + v1;
            rpart[i][1] += v2 + v3;
            cpart0[j8] += v0 + v2;
            cpart1[j8] += v1 + v3;
        }
    }
    #pragma unroll
    for (int i = 0; i < 2; i++) {
        atomicAdd(&rs[m_base + i * 16 + (lane >> 2)], rpart[i][0]);
        atomicAdd(&rs[m_base + i * 16 + (lane >> 2) + 8], rpart[i][1]);
    }
    #pragma unroll
    for (int j8 = 0; j8 < 8; j8++) {
        atomicAdd(&cs[n_base + j8 * 8 + (lane & 3) * 2], cpart0[j8]);
        atomicAdd(&cs[n_base + j8 * 8 + (lane & 3) * 2 + 1], cpart1[j8]);
    }
    __syncthreads();
    if (tid < 128) {
        g_rowm[b * NL + tid] = rs[tid] * (1.0f / NL);
        g_colm[b * NL + tid] = cs[tid] * (1.0f / NL);
    }
}

// ---------------------------------------------------------------------------
// Kernel 4: softmax over precomputed means (tiny)
// ---------------------------------------------------------------------------
__global__ __launch_bounds__(128) void softmax_kernel()
{
    const int b = blockIdx.x, t = threadIdx.x;
    __shared__ float buf[128];
    float v = g_rowm[b * NL + t];
    buf[t] = v; __syncthreads();
    for (int s = 64; s; s >>= 1) { if (t < s) buf[t] = fmaxf(buf[t], buf[t + s]); __syncthreads(); }
    float mx = buf[0]; __syncthreads();
    float e = expf(v - mx);
    buf[t] = e; __syncthreads();
    for (int s = 64; s; s >>= 1) { if (t < s) buf[t] += buf[t + s]; __syncthreads(); }
    g_rows[b * NL + t] = e / buf[0];
    __syncthreads();
    v = g_colm[b * NL + t];
    buf[t] = v; __syncthreads();
    for (int s = 64; s; s >>= 1) { if (t < s) buf[t] = fmaxf(buf[t], buf[t + s]); __syncthreads(); }
    mx = buf[0]; __syncthreads();
    e = expf(v - mx);
    buf[t] = e; __syncthreads();
    for (int s = 64; s; s >>= 1) { if (t < s) buf[t] += buf[t + s]; __syncthreads(); }
    g_cols[b * NL + t] = e / buf[0];
}

// ---------------------------------------------------------------------------
// Kernel 5: weighted reduce from pre-split arrays (sequential, no gather)
// ---------------------------------------------------------------------------
__global__ __launch_bounds__(256) void final_kernel(
    const float* __restrict__ w, const float* __restrict__ bp,
    float* __restrict__ out)
{
    const int b = blockIdx.x, tid = threadIdx.x;
    __shared__ float rw[NL], cw[NL];
    if (tid < NL) { rw[tid] = g_rows[b * NL + tid]; cw[tid] = g_cols[b * NL + tid]; }
    __syncthreads();
    float ax = 0.f, ay = 0.f, bx = 0.f, by = 0.f;
    for (int l = 0; l < NL; l++) {
        size_t o = (size_t)(b * NL + l) * 256 + tid;
        float2 a = unsplit(g_A1h[o], g_A1l[o]);
        float2 bb = unsplit(g_B2h[o], g_B2l[o]);
        ax += rw[l] * a.x;  ay += rw[l] * a.y;
        bx += cw[l] * bb.x; by += cw[l] * bb.y;
    }
    float2 wv = ((const float2*)w)[tid];
    float part = (ax * bx * wv.x + ay * by * wv.y) * (g_inv_na[b] * g_inv_nb[b]);
    __shared__ float sh[8];
    #pragma unroll
    for (int o = 16; o; o >>= 1) part += __shfl_xor_sync(0xffffffffu, part, o);
    if ((tid & 31) == 0) sh[tid >> 5] = part;
    __syncthreads();
    if (tid < 8) {
        part = sh[tid];
        #pragma unroll
        for (int o = 4; o; o >>= 1) part += __shfl_xor_sync(0xffu, part, o);
        if (tid == 0) out[b] = part + bp[0];
    }
}

// ---------------------------------------------------------------------------
extern "C" void kernel_launch(void* const* d_in, const int* in_sizes, int n_in,
                              void* d_out, int out_size)
{
    (void)in_sizes; (void)n_in; (void)out_size;
    const int*   t1c = (const int*)d_in[2];
    const int*   t2c = (const int*)d_in[3];
    const float* E   = (const float*)d_in[4];
    const float* M   = (const float*)d_in[5];
    const float* w   = (const float*)d_in[6];
    const float* bp  = (const float*)d_in[7];
    float* out  = (float*)d_out;
    float* outS = out + NB;   // output = concat(logits[512], S[512*128*128])

    cudaFuncSetAttribute(gemm1_kernel, cudaFuncAttributeMaxDynamicSharedMemorySize, G1_SMEM);
    cudaFuncSetAttribute(gemm2_kernel, cudaFuncAttributeMaxDynamicSharedMemorySize, G2_SMEM);

    prep_mt_kernel<<<dim3(16, 16), 256>>>(M);
    prep_kernel<<<NB, 256>>>(t1c, t2c, E);
    gemm1_kernel<<<dim3(2, 512), 512, G1_SMEM>>>();
    gemm2_kernel<<<NB, 256, G2_SMEM>>>(outS);
    softmax_kernel<<<NB, 128>>>();
    final_kernel<<<NB, 256>>>(w, bp, out);
}

// round 9
// speedup vs baseline: 2.3385x; 1.0090x over previous
#include <cuda_runtime.h>
#include <cuda_bf16.h>
#include <math.h>
#include <stdint.h>

#define NB 512
#define NL 128
#define ND 512
#define NROWS ((size_t)NB * NL)   // 65536

// ---------------- scratch (static device globals) ----------------
// packed 2x bf16 per uint32; row = 256 uint32 = 512 cols
__device__ uint32_t g_A1h[NROWS * 256], g_A1l[NROWS * 256];  // gather(E,t1) hi/lo
__device__ uint32_t g_B2h[NROWS * 256], g_B2l[NROWS * 256];  // gather(E,t2) hi/lo
__device__ uint32_t g_Ch [NROWS * 256], g_Cl [NROWS * 256];  // C = A1 @ M hi/lo
__device__ uint32_t g_Mth[ND * 256],    g_Mtl[ND * 256];     // Mt[n][k] hi/lo
__device__ float g_inv_na[NB], g_inv_nb[NB];
__device__ float g_rowm[NB * NL], g_colm[NB * NL];
__device__ float g_rows[NB * NL], g_cols[NB * NL];

// ---------------- helpers ----------------
__device__ __forceinline__ uint32_t smem_u32(const void* p) {
    uint32_t a;
    asm("{ .reg .u64 t; cvta.to.shared.u64 t, %1; cvt.u32.u64 %0, t; }" : "=r"(a) : "l"(p));
    return a;
}
__device__ __forceinline__ uint32_t swz(uint32_t o) { return o ^ ((o >> 3) & 0x70); }

#define CP16(dst, src) \
    asm volatile("cp.async.cg.shared.global [%0], [%1], 16;" :: "r"(dst), "l"(src))
#define CP_COMMIT() asm volatile("cp.async.commit_group;" ::: "memory")
#define CP_WAIT(n)  asm volatile("cp.async.wait_group %0;" :: "n"(n) : "memory")

__device__ __forceinline__ void ldm_x4(uint32_t* r, uint32_t addr) {
    asm volatile("ldmatrix.sync.aligned.m8n8.x4.shared.b16 {%0,%1,%2,%3}, [%4];"
        : "=r"(r[0]), "=r"(r[1]), "=r"(r[2]), "=r"(r[3]) : "r"(addr));
}
__device__ __forceinline__ void mma_bf16(float* c, const uint32_t* a, const uint32_t* b) {
    asm volatile("mma.sync.aligned.m16n8k16.row.col.f32.bf16.bf16.f32 "
        "{%0,%1,%2,%3}, {%4,%5,%6,%7}, {%8,%9}, {%0,%1,%2,%3};"
        : "+f"(c[0]), "+f"(c[1]), "+f"(c[2]), "+f"(c[3])
        : "r"(a[0]), "r"(a[1]), "r"(a[2]), "r"(a[3]), "r"(b[0]), "r"(b[1]));
}

// bf16 split: x ~= hi + lo, packed pairs
__device__ __forceinline__ void split2(float a, float b, uint32_t& h, uint32_t& l) {
    __nv_bfloat16 ha = __float2bfloat16_rn(a), hb = __float2bfloat16_rn(b);
    __nv_bfloat16 la = __float2bfloat16_rn(a - __bfloat162float(ha));
    __nv_bfloat16 lb = __float2bfloat16_rn(b - __bfloat162float(hb));
    h = ((uint32_t)__bfloat16_as_ushort(hb) << 16) | (uint32_t)__bfloat16_as_ushort(ha);
    l = ((uint32_t)__bfloat16_as_ushort(lb) << 16) | (uint32_t)__bfloat16_as_ushort(la);
}
__device__ __forceinline__ float2 unsplit(uint32_t h, uint32_t l) {
    __nv_bfloat162 H = *reinterpret_cast<__nv_bfloat162*>(&h);
    __nv_bfloat162 L = *reinterpret_cast<__nv_bfloat162*>(&l);
    return make_float2(__bfloat162float(H.x) + __bfloat162float(L.x),
                       __bfloat162float(H.y) + __bfloat162float(L.y));
}

// One K=64 chunk, warp tile 32x64. Stage: Ah @ 0, Al @ +16K, Bh @ +b_off, Bl @ +b_off+b_delta.
__device__ __forceinline__ void compute_chunk(uint32_t st, int lane, int m_base,
                                              int n_base, float acc[2][8][4],
                                              uint32_t b_off, uint32_t b_delta) {
    const int lrow = lane & 7, lmat = lane >> 3;
    const uint32_t a_row = (uint32_t)(m_base + (lmat & 1) * 8 + lrow) * 128;
    const uint32_t a_kb  = (uint32_t)((lmat >> 1) * 8) * 2;
    const uint32_t b_row = (uint32_t)(n_base + (lmat >> 1) * 8 + lrow) * 128;
    const uint32_t b_kb  = (uint32_t)((lmat & 1) * 8) * 2;
    #pragma unroll
    for (int ks = 0; ks < 4; ks++) {
        uint32_t Ah[2][4], Al[2][4];
        #pragma unroll
        for (int i = 0; i < 2; i++) {
            uint32_t off = swz(a_row + (uint32_t)i * 2048 + a_kb + ks * 32);
            ldm_x4(Ah[i], st + off);
            ldm_x4(Al[i], st + 16384 + off);
        }
        #pragma unroll
        for (int j = 0; j < 4; j++) {
            uint32_t off = swz(b_row + (uint32_t)j * 2048 + b_kb + ks * 32);
            uint32_t Bh[4], Bl[4];
            ldm_x4(Bh, st + b_off + off);
            ldm_x4(Bl, st + b_off + b_delta + off);
            #pragma unroll
            for (int i = 0; i < 2; i++) {
                mma_bf16(acc[i][2*j],   Ah[i], &Bh[0]);
                mma_bf16(acc[i][2*j+1], Ah[i], &Bh[2]);
                mma_bf16(acc[i][2*j],   Ah[i], &Bl[0]);
                mma_bf16(acc[i][2*j+1], Ah[i], &Bl[2]);
                mma_bf16(acc[i][2*j],   Al[i], &Bh[0]);
                mma_bf16(acc[i][2*j+1], Al[i], &Bh[2]);
            }
        }
    }
}

// One K=64 chunk, warp tile 32x32 (for gemm2, 16 warps)
__device__ __forceinline__ void compute_chunk32(uint32_t st, int lane, int m_base,
                                                int n_base, float acc[2][4][4],
                                                uint32_t b_off, uint32_t b_delta) {
    const int lrow = lane & 7, lmat = lane >> 3;
    const uint32_t a_row = (uint32_t)(m_base + (lmat & 1) * 8 + lrow) * 128;
    const uint32_t a_kb  = (uint32_t)((lmat >> 1) * 8) * 2;
    const uint32_t b_row = (uint32_t)(n_base + (lmat >> 1) * 8 + lrow) * 128;
    const uint32_t b_kb  = (uint32_t)((lmat & 1) * 8) * 2;
    #pragma unroll
    for (int ks = 0; ks < 4; ks++) {
        uint32_t Ah[2][4], Al[2][4];
        #pragma unroll
        for (int i = 0; i < 2; i++) {
            uint32_t off = swz(a_row + (uint32_t)i * 2048 + a_kb + ks * 32);
            ldm_x4(Ah[i], st + off);
            ldm_x4(Al[i], st + 16384 + off);
        }
        #pragma unroll
        for (int j = 0; j < 2; j++) {
            uint32_t off = swz(b_row + (uint32_t)j * 2048 + b_kb + ks * 32);
            uint32_t Bh[4], Bl[4];
            ldm_x4(Bh, st + b_off + off);
            ldm_x4(Bl, st + b_off + b_delta + off);
            #pragma unroll
            for (int i = 0; i < 2; i++) {
                mma_bf16(acc[i][2*j],   Ah[i], &Bh[0]);
                mma_bf16(acc[i][2*j+1], Ah[i], &Bh[2]);
                mma_bf16(acc[i][2*j],   Ah[i], &Bl[0]);
                mma_bf16(acc[i][2*j+1], Ah[i], &Bl[2]);
                mma_bf16(acc[i][2*j],   Al[i], &Bh[0]);
                mma_bf16(acc[i][2*j+1], Al[i], &Bh[2]);
            }
        }
    }
}

// ---------------------------------------------------------------------------
// Kernel 0: transpose + split att_mat -> g_Mth/g_Mtl (Mt[n][k] = M[k][n])
// ---------------------------------------------------------------------------
__global__ __launch_bounds__(256) void prep_mt_kernel(const float* __restrict__ M) {
    __shared__ float t[32][33];
    const int n0 = blockIdx.x * 32, k0 = blockIdx.y * 32;
    const int tid = threadIdx.x;
    const int tx = tid & 31, ty = tid >> 5;
    #pragma unroll
    for (int j = 0; j < 32; j += 8)
        t[ty + j][tx] = M[(size_t)(k0 + ty + j) * ND + n0 + tx];
    __syncthreads();
    #pragma unroll
    for (int rep = 0; rep < 2; rep++) {
        int idx = rep * 256 + tid;
        int nl = idx >> 4, kp = idx & 15;
        uint32_t h, l;
        split2(t[2 * kp][nl], t[2 * kp + 1][nl], h, l);
        size_t o = (size_t)(n0 + nl) * 256 + (k0 >> 1) + kp;
        g_Mth[o] = h;
        g_Mtl[o] = l;
    }
}

// ---------------------------------------------------------------------------
// Kernel 1: gather + split + norms (fused)
// ---------------------------------------------------------------------------
__global__ __launch_bounds__(256) void prep_kernel(
    const int* __restrict__ t1c, const int* __restrict__ t2c,
    const float* __restrict__ E)
{
    const int b = blockIdx.x, tid = threadIdx.x;
    __shared__ int i1s[NL], i2s[NL];
    if (tid < NL) { i1s[tid] = t1c[b * NL + tid]; i2s[tid] = t2c[b * NL + tid]; }
    __syncthreads();
    float s1 = 0.f, s2 = 0.f;
    #pragma unroll 2
    for (int l = 0; l < NL; l++) {
        float2 v1 = ((const float2*)(E + (size_t)i1s[l] * ND))[tid];
        float2 v2 = ((const float2*)(E + (size_t)i2s[l] * ND))[tid];
        s1 += v1.x * v1.x + v1.y * v1.y;
        s2 += v2.x * v2.x + v2.y * v2.y;
        size_t o = (size_t)(b * NL + l) * 256 + tid;
        uint32_t h, lo;
        split2(v1.x, v1.y, h, lo); g_A1h[o] = h; g_A1l[o] = lo;
        split2(v2.x, v2.y, h, lo); g_B2h[o] = h; g_B2l[o] = lo;
    }
    __shared__ float sh1[8], sh2[8];
    #pragma unroll
    for (int o = 16; o; o >>= 1) {
        s1 += __shfl_xor_sync(0xffffffffu, s1, o);
        s2 += __shfl_xor_sync(0xffffffffu, s2, o);
    }
    if ((tid & 31) == 0) { sh1[tid >> 5] = s1; sh2[tid >> 5] = s2; }
    __syncthreads();
    if (tid < 8) {
        s1 = sh1[tid]; s2 = sh2[tid];
        #pragma unroll
        for (int o = 4; o; o >>= 1) {
            s1 += __shfl_xor_sync(0xffu, s1, o);
            s2 += __shfl_xor_sync(0xffu, s2, o);
        }
        if (tid == 0) { g_inv_na[b] = rsqrtf(s1); g_inv_nb[b] = rsqrtf(s2); }
    }
}

// ---------------------------------------------------------------------------
// Kernel 2: GEMM1 — C = A1 @ Mt^T, 128x256 block tile, 512 thr, cp.async 2-stage
// ---------------------------------------------------------------------------
#define G1_STAGE 98304
#define G1_SMEM  (2 * G1_STAGE + 1024)

__global__ __launch_bounds__(512, 1) void gemm1_kernel()
{
    extern __shared__ char smem_raw[];
    const uint32_t sb_raw = smem_u32(smem_raw);
    const uint32_t sb = (sb_raw + 1023) & ~1023u;
    const int tid = threadIdx.x;
    const int m0 = blockIdx.y * 128, n0 = blockIdx.x * 256;

    const char* srcAh = (const char*)g_A1h + (size_t)m0 * 1024;
    const char* srcAl = (const char*)g_A1l + (size_t)m0 * 1024;
    const char* srcBh = (const char*)g_Mth + (size_t)n0 * 1024;
    const char* srcBl = (const char*)g_Mtl + (size_t)n0 * 1024;

    auto load_stage = [&](int c, int s) {
        const uint32_t stg = sb + s * G1_STAGE;
        #pragma unroll
        for (int q = 0; q < 2; q++) {     // A: 128 rows x 8 segs, hi+lo
            int sid = tid + q * 512;
            int r = sid >> 3, seg = sid & 7;
            uint32_t dst = stg + swz((uint32_t)(r * 128 + seg * 16));
            size_t so = (size_t)r * 1024 + c * 128 + seg * 16;
            CP16(dst, srcAh + so);
            CP16(dst + 16384, srcAl + so);
        }
        #pragma unroll
        for (int q = 0; q < 4; q++) {     // B: 256 rows x 8 segs, hi+lo
            int sid = tid + q * 512;
            int r = sid >> 3, seg = sid & 7;
            uint32_t dst = stg + 32768 + swz((uint32_t)(r * 128 + seg * 16));
            size_t so = (size_t)r * 1024 + c * 128 + seg * 16;
            CP16(dst, srcBh + so);
            CP16(dst + 32768, srcBl + so);
        }
    };

    float acc[2][8][4];
    #pragma unroll
    for (int i = 0; i < 2; i++)
        #pragma unroll
        for (int j = 0; j < 8; j++)
            #pragma unroll
            for (int q = 0; q < 4; q++) acc[i][j][q] = 0.f;

    load_stage(0, 0); CP_COMMIT();
    load_stage(1, 1); CP_COMMIT();
    CP_WAIT(1); __syncthreads();

    const int wid = tid >> 5, lane = tid & 31;
    const int m_base = (wid >> 2) * 32, n_base = (wid & 3) * 64;

    for (int c = 0; c < 8; c++) {
        compute_chunk(sb + (c & 1) * G1_STAGE, lane, m_base, n_base, acc, 32768, 32768);
        __syncthreads();
        if (c + 2 < 8) { load_stage(c + 2, c & 1); CP_COMMIT(); CP_WAIT(1); }
        else if (c == 6) { CP_WAIT(0); }
        __syncthreads();
    }

    // epilogue: split acc -> g_Ch / g_Cl
    #pragma unroll
    for (int i = 0; i < 2; i++) {
        int gr = m0 + m_base + i * 16 + (lane >> 2);
        #pragma unroll
        for (int j8 = 0; j8 < 8; j8++) {
            int gc = n0 + n_base + j8 * 8 + (lane & 3) * 2;
            size_t o0 = (size_t)gr * 256 + (gc >> 1);
            size_t o1 = (size_t)(gr + 8) * 256 + (gc >> 1);
            uint32_t h, l;
            split2(acc[i][j8][0], acc[i][j8][1], h, l);
            g_Ch[o0] = h; g_Cl[o0] = l;
            split2(acc[i][j8][2], acc[i][j8][3], h, l);
            g_Ch[o1] = h; g_Cl[o1] = l;
        }
    }
}

// ---------------------------------------------------------------------------
// Kernel 3: GEMM2 — S[b] = tanh(scale * C[b] @ B2[b]^T), fused means
//   512 threads, 16 warps (4x4), warp tile 32x32; 3-stage x 64KB cp.async
// ---------------------------------------------------------------------------
#define G2_STAGE 65536
#define G2_SMEM  (3 * G2_STAGE + 1024)

__global__ __launch_bounds__(512, 1) void gemm2_kernel(float* __restrict__ outS)
{
    extern __shared__ char smem_raw[];
    const uint32_t sb_raw = smem_u32(smem_raw);
    const uint32_t sb = (sb_raw + 1023) & ~1023u;
    char* smem = smem_raw + (sb - sb_raw);
    const int tid = threadIdx.x;
    const int b = blockIdx.x;

    const char* srcAh = (const char*)g_Ch  + (size_t)b * NL * 1024;
    const char* srcAl = (const char*)g_Cl  + (size_t)b * NL * 1024;
    const char* srcBh = (const char*)g_B2h + (size_t)b * NL * 1024;
    const char* srcBl = (const char*)g_B2l + (size_t)b * NL * 1024;

    auto load_stage = [&](int c, int s) {
        const uint32_t stg = sb + s * G2_STAGE;
        #pragma unroll
        for (int q = 0; q < 2; q++) {
            int sid = tid + q * 512;
            int r = sid >> 3, seg = sid & 7;
            uint32_t dst = stg + swz((uint32_t)(r * 128 + seg * 16));
            size_t so = (size_t)r * 1024 + c * 128 + seg * 16;
            CP16(dst, srcAh + so);
            CP16(dst + 16384, srcAl + so);
            CP16(dst + 32768, srcBh + so);
            CP16(dst + 49152, srcBl + so);
        }
    };

    float acc[2][4][4];
    #pragma unroll
    for (int i = 0; i < 2; i++)
        #pragma unroll
        for (int j = 0; j < 4; j++)
            #pragma unroll
            for (int q = 0; q < 4; q++) acc[i][j][q] = 0.f;

    load_stage(0, 0); CP_COMMIT();
    load_stage(1, 1); CP_COMMIT();
    load_stage(2, 2); CP_COMMIT();
    CP_WAIT(2); __syncthreads();

    const int wid = tid >> 5, lane = tid & 31;
    const int m_base = (wid >> 2) * 32, n_base = (wid & 3) * 32;

    for (int c = 0; c < 8; c++) {
        compute_chunk32(sb + (c % 3) * G2_STAGE, lane, m_base, n_base, acc, 32768, 16384);
        __syncthreads();
        if (c + 3 < 8)      { load_stage(c + 3, c % 3); CP_COMMIT(); CP_WAIT(2); }
        else if (c == 5)    { CP_WAIT(1); }
        else if (c == 6)    { CP_WAIT(0); }
        __syncthreads();
    }

    // epilogue: tanh + S store + fused row/col means
    float* rs = (float*)smem;
    float* cs = rs + 128;
    if (tid < 128) { rs[tid] = 0.f; cs[tid] = 0.f; }
    __syncthreads();

    const float scale = g_inv_na[b] * g_inv_nb[b];
    float* Sb = outS + (size_t)b * NL * NL;
    float cpart0[4], cpart1[4];
    #pragma unroll
    for (int j8 = 0; j8 < 4; j8++) { cpart0[j8] = 0.f; cpart1[j8] = 0.f; }
    float rpart[2][2] = {{0.f, 0.f}, {0.f, 0.f}};

    #pragma unroll
    for (int i = 0; i < 2; i++) {
        int r0 = m_base + i * 16 + (lane >> 2);
        #pragma unroll
        for (int j8 = 0; j8 < 4; j8++) {
            int col = n_base + j8 * 8 + (lane & 3) * 2;
            float v0 = tanhf(acc[i][j8][0] * scale);
            float v1 = tanhf(acc[i][j8][1] * scale);
            float v2 = tanhf(acc[i][j8][2] * scale);
            float v3 = tanhf(acc[i][j8][3] * scale);
            float* p = Sb + (size_t)r0 * NL + col;
            *(float2*)p = make_float2(v0, v1);
            *(float2*)(p + 8 * NL) = make_float2(v2, v3);
            rpart[i][0] += v0 + v1;
            rpart[i][1] += v2 + v3;
            cpart0[j8] += v0 + v2;
            cpart1[j8] += v1 + v3;
        }
    }
    #pragma unroll
    for (int i = 0; i < 2; i++) {
        atomicAdd(&rs[m_base + i * 16 + (lane >> 2)], rpart[i][0]);
        atomicAdd(&rs[m_base + i * 16 + (lane >> 2) + 8], rpart[i][1]);
    }
    #pragma unroll
    for (int j8 = 0; j8 < 4; j8++) {
        atomicAdd(&cs[n_base + j8 * 8 + (lane & 3) * 2], cpart0[j8]);
        atomicAdd(&cs[n_base + j8 * 8 + (lane & 3) * 2 + 1], cpart1[j8]);
    }
    __syncthreads();
    if (tid < 128) {
        g_rowm[b * NL + tid] = rs[tid] * (1.0f / NL);
        g_colm[b * NL + tid] = cs[tid] * (1.0f / NL);
    }
}

// ---------------------------------------------------------------------------
// Kernel 4: softmax over precomputed means (tiny)
// ---------------------------------------------------------------------------
__global__ __launch_bounds__(128) void softmax_kernel()
{
    const int b = blockIdx.x, t = threadIdx.x;
    __shared__ float buf[128];
    float v = g_rowm[b * NL + t];
    buf[t] = v; __syncthreads();
    for (int s = 64; s; s >>= 1) { if (t < s) buf[t] = fmaxf(buf[t], buf[t + s]); __syncthreads(); }
    float mx = buf[0]; __syncthreads();
    float e = expf(v - mx);
    buf[t] = e; __syncthreads();
    for (int s = 64; s; s >>= 1) { if (t < s) buf[t] += buf[t + s]; __syncthreads(); }
    g_rows[b * NL + t] = e / buf[0];
    __syncthreads();
    v = g_colm[b * NL + t];
    buf[t] = v; __syncthreads();
    for (int s = 64; s; s >>= 1) { if (t < s) buf[t] = fmaxf(buf[t], buf[t + s]); __syncthreads(); }
    mx = buf[0]; __syncthreads();
    e = expf(v - mx);
    buf[t] = e; __syncthreads();
    for (int s = 64; s; s >>= 1) { if (t < s) buf[t] += buf[t + s]; __syncthreads(); }
    g_cols[b * NL + t] = e / buf[0];
}

// ---------------------------------------------------------------------------
// Kernel 5: weighted reduce from pre-split arrays (sequential, no gather)
// ---------------------------------------------------------------------------
__global__ __launch_bounds__(256) void final_kernel(
    const float* __restrict__ w, const float* __restrict__ bp,
    float* __restrict__ out)
{
    const int b = blockIdx.x, tid = threadIdx.x;
    __shared__ float rw[NL], cw[NL];
    if (tid < NL) { rw[tid] = g_rows[b * NL + tid]; cw[tid] = g_cols[b * NL + tid]; }
    __syncthreads();
    float ax = 0.f, ay = 0.f, bx = 0.f, by = 0.f;
    #pragma unroll 4
    for (int l = 0; l < NL; l++) {
        size_t o = (size_t)(b * NL + l) * 256 + tid;
        float2 a = unsplit(g_A1h[o], g_A1l[o]);
        float2 bb = unsplit(g_B2h[o], g_B2l[o]);
        ax += rw[l] * a.x;  ay += rw[l] * a.y;
        bx += cw[l] * bb.x; by += cw[l] * bb.y;
    }
    float2 wv = ((const float2*)w)[tid];
    float part = (ax * bx * wv.x + ay * by * wv.y) * (g_inv_na[b] * g_inv_nb[b]);
    __shared__ float sh[8];
    #pragma unroll
    for (int o = 16; o; o >>= 1) part += __shfl_xor_sync(0xffffffffu, part, o);
    if ((tid & 31) == 0) sh[tid >> 5] = part;
    __syncthreads();
    if (tid < 8) {
        part = sh[tid];
        #pragma unroll
        for (int o = 4; o; o >>= 1) part += __shfl_xor_sync(0xffu, part, o);
        if (tid == 0) out[b] = part + bp[0];
    }
}

// ---------------------------------------------------------------------------
extern "C" void kernel_launch(void* const* d_in, const int* in_sizes, int n_in,
                              void* d_out, int out_size)
{
    (void)in_sizes; (void)n_in; (void)out_size;
    const int*   t1c = (const int*)d_in[2];
    const int*   t2c = (const int*)d_in[3];
    const float* E   = (const float*)d_in[4];
    const float* M   = (const float*)d_in[5];
    const float* w   = (const float*)d_in[6];
    const float* bp  = (const float*)d_in[7];
    float* out  = (float*)d_out;
    float* outS = out + NB;   // output = concat(logits[512], S[512*128*128])

    cudaFuncSetAttribute(gemm1_kernel, cudaFuncAttributeMaxDynamicSharedMemorySize, G1_SMEM);
    cudaFuncSetAttribute(gemm2_kernel, cudaFuncAttributeMaxDynamicSharedMemorySize, G2_SMEM);

    prep_mt_kernel<<<dim3(16, 16), 256>>>(M);
    prep_kernel<<<NB, 256>>>(t1c, t2c, E);
    gemm1_kernel<<<dim3(2, 512), 512, G1_SMEM>>>();
    gemm2_kernel<<<NB, 512, G2_SMEM>>>(outS);
    softmax_kernel<<<NB, 128>>>();
    final_kernel<<<NB, 256>>>(w, bp, out);
}

// round 10
// speedup vs baseline: 3.0024x; 1.2839x over previous
#include <cuda_runtime.h>
#include <cuda_fp16.h>
#include <math.h>
#include <stdint.h>

#define NB 512
#define NL 128
#define ND 512
#define NROWS ((size_t)NB * NL)   // 65536

// ---------------- scratch (static device globals) ----------------
// packed 2x fp16 per uint32; row = 256 uint32 = 512 cols = 1024 B
__device__ uint32_t g_A1h[NROWS * 256];                      // gather(E,t1) fp16
__device__ uint32_t g_B2h[NROWS * 256];                      // gather(E,t2) fp16
__device__ uint32_t g_Ch [NROWS * 256], g_Cl [NROWS * 256];  // C split hi/lo
__device__ uint32_t g_Mth[ND * 256],    g_Mtl[ND * 256];     // Mt[n][k] split
__device__ float g_inv_na[NB], g_inv_nb[NB];
__device__ float g_rowm[NB * NL], g_colm[NB * NL];
__device__ float g_rows[NB * NL], g_cols[NB * NL];

// ---------------- helpers ----------------
__device__ __forceinline__ uint32_t smem_u32(const void* p) {
    uint32_t a;
    asm("{ .reg .u64 t; cvta.to.shared.u64 t, %1; cvt.u32.u64 %0, t; }" : "=r"(a) : "l"(p));
    return a;
}
__device__ __forceinline__ uint32_t swz(uint32_t o) { return o ^ ((o >> 3) & 0x70); }

#define CP16(dst, src) \
    asm volatile("cp.async.cg.shared.global [%0], [%1], 16;" :: "r"(dst), "l"(src))
#define CP_COMMIT() asm volatile("cp.async.commit_group;" ::: "memory")
#define CP_WAIT(n)  asm volatile("cp.async.wait_group %0;" :: "n"(n) : "memory")

__device__ __forceinline__ void ldm_x4(uint32_t* r, uint32_t addr) {
    asm volatile("ldmatrix.sync.aligned.m8n8.x4.shared.b16 {%0,%1,%2,%3}, [%4];"
        : "=r"(r[0]), "=r"(r[1]), "=r"(r[2]), "=r"(r[3]) : "r"(addr));
}
__device__ __forceinline__ void mma_f16(float* c, const uint32_t* a, const uint32_t* b) {
    asm volatile("mma.sync.aligned.m16n8k16.row.col.f32.f16.f16.f32 "
        "{%0,%1,%2,%3}, {%4,%5,%6,%7}, {%8,%9}, {%0,%1,%2,%3};"
        : "+f"(c[0]), "+f"(c[1]), "+f"(c[2]), "+f"(c[3])
        : "r"(a[0]), "r"(a[1]), "r"(a[2]), "r"(a[3]), "r"(b[0]), "r"(b[1]));
}

// fp16 split: x ~= hi + lo (22-bit effective mantissa)
__device__ __forceinline__ void split2h(float a, float b, uint32_t& h, uint32_t& l) {
    __half ha = __float2half_rn(a), hb = __float2half_rn(b);
    __half la = __float2half_rn(a - __half2float(ha));
    __half lb = __float2half_rn(b - __half2float(hb));
    h = ((uint32_t)__half_as_ushort(hb) << 16) | (uint32_t)__half_as_ushort(ha);
    l = ((uint32_t)__half_as_ushort(lb) << 16) | (uint32_t)__half_as_ushort(la);
}
__device__ __forceinline__ uint32_t packh(float a, float b) {
    return ((uint32_t)__half_as_ushort(__float2half_rn(b)) << 16) |
           (uint32_t)__half_as_ushort(__float2half_rn(a));
}

// GEMM1 chunk: warp tile 32x64; A single fp16 @ 0, Bh @ +16K, Bl @ +48K
__device__ __forceinline__ void chunk_g1(uint32_t st, int lane, int m_base,
                                         int n_base, float acc[2][8][4]) {
    const int lrow = lane & 7, lmat = lane >> 3;
    const uint32_t a_row = (uint32_t)(m_base + (lmat & 1) * 8 + lrow) * 128;
    const uint32_t a_kb  = (uint32_t)((lmat >> 1) * 8) * 2;
    const uint32_t b_row = (uint32_t)(n_base + (lmat >> 1) * 8 + lrow) * 128;
    const uint32_t b_kb  = (uint32_t)((lmat & 1) * 8) * 2;
    #pragma unroll
    for (int ks = 0; ks < 4; ks++) {
        uint32_t Af[2][4];
        #pragma unroll
        for (int i = 0; i < 2; i++)
            ldm_x4(Af[i], st + swz(a_row + (uint32_t)i * 2048 + a_kb + ks * 32));
        #pragma unroll
        for (int j = 0; j < 4; j++) {
            uint32_t off = swz(b_row + (uint32_t)j * 2048 + b_kb + ks * 32);
            uint32_t Bh[4], Bl[4];
            ldm_x4(Bh, st + 16384 + off);
            ldm_x4(Bl, st + 49152 + off);
            #pragma unroll
            for (int i = 0; i < 2; i++) {
                mma_f16(acc[i][2*j],   Af[i], &Bh[0]);
                mma_f16(acc[i][2*j+1], Af[i], &Bh[2]);
                mma_f16(acc[i][2*j],   Af[i], &Bl[0]);
                mma_f16(acc[i][2*j+1], Af[i], &Bl[2]);
            }
        }
    }
}

// GEMM2 chunk: warp tile 32x32; Ch @ 0, Cl @ +16K, B single fp16 @ +32K
__device__ __forceinline__ void chunk_g2(uint32_t st, int lane, int m_base,
                                         int n_base, float acc[2][4][4]) {
    const int lrow = lane & 7, lmat = lane >> 3;
    const uint32_t a_row = (uint32_t)(m_base + (lmat & 1) * 8 + lrow) * 128;
    const uint32_t a_kb  = (uint32_t)((lmat >> 1) * 8) * 2;
    const uint32_t b_row = (uint32_t)(n_base + (lmat >> 1) * 8 + lrow) * 128;
    const uint32_t b_kb  = (uint32_t)((lmat & 1) * 8) * 2;
    #pragma unroll
    for (int ks = 0; ks < 4; ks++) {
        uint32_t Chf[2][4], Clf[2][4];
        #pragma unroll
        for (int i = 0; i < 2; i++) {
            uint32_t off = swz(a_row + (uint32_t)i * 2048 + a_kb + ks * 32);
            ldm_x4(Chf[i], st + off);
            ldm_x4(Clf[i], st + 16384 + off);
        }
        #pragma unroll
        for (int j = 0; j < 2; j++) {
            uint32_t off = swz(b_row + (uint32_t)j * 2048 + b_kb + ks * 32);
            uint32_t Bf[4];
            ldm_x4(Bf, st + 32768 + off);
            #pragma unroll
            for (int i = 0; i < 2; i++) {
                mma_f16(acc[i][2*j],   Chf[i], &Bf[0]);
                mma_f16(acc[i][2*j+1], Chf[i], &Bf[2]);
                mma_f16(acc[i][2*j],   Clf[i], &Bf[0]);
                mma_f16(acc[i][2*j+1], Clf[i], &Bf[2]);
            }
        }
    }
}

// ---------------------------------------------------------------------------
// Kernel 0: transpose + fp16-split att_mat -> g_Mth/g_Mtl (Mt[n][k] = M[k][n])
// ---------------------------------------------------------------------------
__global__ __launch_bounds__(256) void prep_mt_kernel(const float* __restrict__ M) {
    __shared__ float t[32][33];
    const int n0 = blockIdx.x * 32, k0 = blockIdx.y * 32;
    const int tid = threadIdx.x;
    const int tx = tid & 31, ty = tid >> 5;
    #pragma unroll
    for (int j = 0; j < 32; j += 8)
        t[ty + j][tx] = M[(size_t)(k0 + ty + j) * ND + n0 + tx];
    __syncthreads();
    #pragma unroll
    for (int rep = 0; rep < 2; rep++) {
        int idx = rep * 256 + tid;
        int nl = idx >> 4, kp = idx & 15;
        uint32_t h, l;
        split2h(t[2 * kp][nl], t[2 * kp + 1][nl], h, l);
        size_t o = (size_t)(n0 + nl) * 256 + (k0 >> 1) + kp;
        g_Mth[o] = h;
        g_Mtl[o] = l;
    }
}

// ---------------------------------------------------------------------------
// Kernel 1: gather + fp16-pack + norms (fused)
// ---------------------------------------------------------------------------
__global__ __launch_bounds__(256) void prep_kernel(
    const int* __restrict__ t1c, const int* __restrict__ t2c,
    const float* __restrict__ E)
{
    const int b = blockIdx.x, tid = threadIdx.x;
    __shared__ int i1s[NL], i2s[NL];
    if (tid < NL) { i1s[tid] = t1c[b * NL + tid]; i2s[tid] = t2c[b * NL + tid]; }
    __syncthreads();
    float s1 = 0.f, s2 = 0.f;
    #pragma unroll 2
    for (int l = 0; l < NL; l++) {
        float2 v1 = ((const float2*)(E + (size_t)i1s[l] * ND))[tid];
        float2 v2 = ((const float2*)(E + (size_t)i2s[l] * ND))[tid];
        s1 += v1.x * v1.x + v1.y * v1.y;
        s2 += v2.x * v2.x + v2.y * v2.y;
        size_t o = (size_t)(b * NL + l) * 256 + tid;
        g_A1h[o] = packh(v1.x, v1.y);
        g_B2h[o] = packh(v2.x, v2.y);
    }
    __shared__ float sh1[8], sh2[8];
    #pragma unroll
    for (int o = 16; o; o >>= 1) {
        s1 += __shfl_xor_sync(0xffffffffu, s1, o);
        s2 += __shfl_xor_sync(0xffffffffu, s2, o);
    }
    if ((tid & 31) == 0) { sh1[tid >> 5] = s1; sh2[tid >> 5] = s2; }
    __syncthreads();
    if (tid < 8) {
        s1 = sh1[tid]; s2 = sh2[tid];
        #pragma unroll
        for (int o = 4; o; o >>= 1) {
            s1 += __shfl_xor_sync(0xffu, s1, o);
            s2 += __shfl_xor_sync(0xffu, s2, o);
        }
        if (tid == 0) { g_inv_na[b] = rsqrtf(s1); g_inv_nb[b] = rsqrtf(s2); }
    }
}

// ---------------------------------------------------------------------------
// Kernel 2: GEMM1 — C = A1 @ Mt^T (A1 fp16, Mt split), 128x256 tile, 512 thr
//   stage: A 16K | Bh 32K | Bl 32K = 80KB, 2 stages
// ---------------------------------------------------------------------------
#define G1_STAGE 81920
#define G1_SMEM  (2 * G1_STAGE + 1024)

__global__ __launch_bounds__(512, 1) void gemm1_kernel()
{
    extern __shared__ char smem_raw[];
    const uint32_t sb_raw = smem_u32(smem_raw);
    const uint32_t sb = (sb_raw + 1023) & ~1023u;
    const int tid = threadIdx.x;
    const int m0 = blockIdx.y * 128, n0 = blockIdx.x * 256;

    const char* srcA  = (const char*)g_A1h + (size_t)m0 * 1024;
    const char* srcBh = (const char*)g_Mth + (size_t)n0 * 1024;
    const char* srcBl = (const char*)g_Mtl + (size_t)n0 * 1024;

    auto load_stage = [&](int c, int s) {
        const uint32_t stg = sb + s * G1_STAGE;
        #pragma unroll
        for (int q = 0; q < 2; q++) {     // A: 128 rows x 8 segs
            int sid = tid + q * 512;
            int r = sid >> 3, seg = sid & 7;
            uint32_t dst = stg + swz((uint32_t)(r * 128 + seg * 16));
            CP16(dst, srcA + (size_t)r * 1024 + c * 128 + seg * 16);
        }
        #pragma unroll
        for (int q = 0; q < 4; q++) {     // B: 256 rows x 8 segs, hi+lo
            int sid = tid + q * 512;
            int r = sid >> 3, seg = sid & 7;
            uint32_t dst = stg + 16384 + swz((uint32_t)(r * 128 + seg * 16));
            size_t so = (size_t)r * 1024 + c * 128 + seg * 16;
            CP16(dst, srcBh + so);
            CP16(dst + 32768, srcBl + so);
        }
    };

    float acc[2][8][4];
    #pragma unroll
    for (int i = 0; i < 2; i++)
        #pragma unroll
        for (int j = 0; j < 8; j++)
            #pragma unroll
            for (int q = 0; q < 4; q++) acc[i][j][q] = 0.f;

    load_stage(0, 0); CP_COMMIT();
    load_stage(1, 1); CP_COMMIT();
    CP_WAIT(1); __syncthreads();

    const int wid = tid >> 5, lane = tid & 31;
    const int m_base = (wid >> 2) * 32, n_base = (wid & 3) * 64;

    for (int c = 0; c < 8; c++) {
        chunk_g1(sb + (c & 1) * G1_STAGE, lane, m_base, n_base, acc);
        __syncthreads();
        if (c + 2 < 8) { load_stage(c + 2, c & 1); CP_COMMIT(); CP_WAIT(1); }
        else if (c == 6) { CP_WAIT(0); }
        __syncthreads();
    }

    // epilogue: fp16-split acc -> g_Ch / g_Cl
    #pragma unroll
    for (int i = 0; i < 2; i++) {
        int gr = m0 + m_base + i * 16 + (lane >> 2);
        #pragma unroll
        for (int j8 = 0; j8 < 8; j8++) {
            int gc = n0 + n_base + j8 * 8 + (lane & 3) * 2;
            size_t o0 = (size_t)gr * 256 + (gc >> 1);
            size_t o1 = (size_t)(gr + 8) * 256 + (gc >> 1);
            uint32_t h, l;
            split2h(acc[i][j8][0], acc[i][j8][1], h, l);
            g_Ch[o0] = h; g_Cl[o0] = l;
            split2h(acc[i][j8][2], acc[i][j8][3], h, l);
            g_Ch[o1] = h; g_Cl[o1] = l;
        }
    }
}

// ---------------------------------------------------------------------------
// Kernel 3: GEMM2 — S[b] = tanh(scale * C[b] @ B2[b]^T), fused means
//   512 thr, 16 warps (4x4), warp tile 32x32; stage Ch|Cl|B2h = 48KB x 3
// ---------------------------------------------------------------------------
#define G2_STAGE 49152
#define G2_SMEM  (3 * G2_STAGE + 1024)

__global__ __launch_bounds__(512, 1) void gemm2_kernel(float* __restrict__ outS)
{
    extern __shared__ char smem_raw[];
    const uint32_t sb_raw = smem_u32(smem_raw);
    const uint32_t sb = (sb_raw + 1023) & ~1023u;
    char* smem = smem_raw + (sb - sb_raw);
    const int tid = threadIdx.x;
    const int b = blockIdx.x;

    const char* srcCh = (const char*)g_Ch  + (size_t)b * NL * 1024;
    const char* srcCl = (const char*)g_Cl  + (size_t)b * NL * 1024;
    const char* srcB  = (const char*)g_B2h + (size_t)b * NL * 1024;

    auto load_stage = [&](int c, int s) {
        const uint32_t stg = sb + s * G2_STAGE;
        #pragma unroll
        for (int q = 0; q < 2; q++) {
            int sid = tid + q * 512;
            int r = sid >> 3, seg = sid & 7;
            uint32_t dst = stg + swz((uint32_t)(r * 128 + seg * 16));
            size_t so = (size_t)r * 1024 + c * 128 + seg * 16;
            CP16(dst, srcCh + so);
            CP16(dst + 16384, srcCl + so);
            CP16(dst + 32768, srcB + so);
        }
    };

    float acc[2][4][4];
    #pragma unroll
    for (int i = 0; i < 2; i++)
        #pragma unroll
        for (int j = 0; j < 4; j++)
            #pragma unroll
            for (int q = 0; q < 4; q++) acc[i][j][q] = 0.f;

    load_stage(0, 0); CP_COMMIT();
    load_stage(1, 1); CP_COMMIT();
    load_stage(2, 2); CP_COMMIT();
    CP_WAIT(2); __syncthreads();

    const int wid = tid >> 5, lane = tid & 31;
    const int m_base = (wid >> 2) * 32, n_base = (wid & 3) * 32;

    for (int c = 0; c < 8; c++) {
        chunk_g2(sb + (c % 3) * G2_STAGE, lane, m_base, n_base, acc);
        __syncthreads();
        if (c + 3 < 8)      { load_stage(c + 3, c % 3); CP_COMMIT(); CP_WAIT(2); }
        else if (c == 5)    { CP_WAIT(1); }
        else if (c == 6)    { CP_WAIT(0); }
        __syncthreads();
    }

    // epilogue: tanh + S store + fused row/col means
    float* rs = (float*)smem;
    float* cs = rs + 128;
    if (tid < 128) { rs[tid] = 0.f; cs[tid] = 0.f; }
    __syncthreads();

    const float scale = g_inv_na[b] * g_inv_nb[b];
    float* Sb = outS + (size_t)b * NL * NL;
    float cpart0[4], cpart1[4];
    #pragma unroll
    for (int j8 = 0; j8 < 4; j8++) { cpart0[j8] = 0.f; cpart1[j8] = 0.f; }
    float rpart[2][2] = {{0.f, 0.f}, {0.f, 0.f}};

    #pragma unroll
    for (int i = 0; i < 2; i++) {
        int r0 = m_base + i * 16 + (lane >> 2);
        #pragma unroll
        for (int j8 = 0; j8 < 4; j8++) {
            int col = n_base + j8 * 8 + (lane & 3) * 2;
            float v0 = tanhf(acc[i][j8][0] * scale);
            float v1 = tanhf(acc[i][j8][1] * scale);
            float v2 = tanhf(acc[i][j8][2] * scale);
            float v3 = tanhf(acc[i][j8][3] * scale);
            float* p = Sb + (size_t)r0 * NL + col;
            *(float2*)p = make_float2(v0, v1);
            *(float2*)(p + 8 * NL) = make_float2(v2, v3);
            rpart[i][0] += v0 + v1;
            rpart[i][1] += v2 + v3;
            cpart0[j8] += v0 + v2;
            cpart1[j8] += v1 + v3;
        }
    }
    #pragma unroll
    for (int i = 0; i < 2; i++) {
        atomicAdd(&rs[m_base + i * 16 + (lane >> 2)], rpart[i][0]);
        atomicAdd(&rs[m_base + i * 16 + (lane >> 2) + 8], rpart[i][1]);
    }
    #pragma unroll
    for (int j8 = 0; j8 < 4; j8++) {
        atomicAdd(&cs[n_base + j8 * 8 + (lane & 3) * 2], cpart0[j8]);
        atomicAdd(&cs[n_base + j8 * 8 + (lane & 3) * 2 + 1], cpart1[j8]);
    }
    __syncthreads();
    if (tid < 128) {
        g_rowm[b * NL + tid] = rs[tid] * (1.0f / NL);
        g_colm[b * NL + tid] = cs[tid] * (1.0f / NL);
    }
}

// ---------------------------------------------------------------------------
// Kernel 4: softmax over precomputed means (tiny)
// ---------------------------------------------------------------------------
__global__ __launch_bounds__(128) void softmax_kernel()
{
    const int b = blockIdx.x, t = threadIdx.x;
    __shared__ float buf[128];
    float v = g_rowm[b * NL + t];
    buf[t] = v; __syncthreads();
    for (int s = 64; s; s >>= 1) { if (t < s) buf[t] = fmaxf(buf[t], buf[t + s]); __syncthreads(); }
    float mx = buf[0]; __syncthreads();
    float e = expf(v - mx);
    buf[t] = e; __syncthreads();
    for (int s = 64; s; s >>= 1) { if (t < s) buf[t] += buf[t + s]; __syncthreads(); }
    g_rows[b * NL + t] = e / buf[0];
    __syncthreads();
    v = g_colm[b * NL + t];
    buf[t] = v; __syncthreads();
    for (int s = 64; s; s >>= 1) { if (t < s) buf[t] = fmaxf(buf[t], buf[t + s]); __syncthreads(); }
    mx = buf[0]; __syncthreads();
    e = expf(v - mx);
    buf[t] = e; __syncthreads();
    for (int s = 64; s; s >>= 1) { if (t < s) buf[t] += buf[t + s]; __syncthreads(); }
    g_cols[b * NL + t] = e / buf[0];
}

// ---------------------------------------------------------------------------
// Kernel 5: weighted re-gather + logits (exact fp32 path)
// ---------------------------------------------------------------------------
__global__ __launch_bounds__(256) void final_kernel(
    const int* __restrict__ t1c, const int* __restrict__ t2c,
    const float* __restrict__ E, const float* __restrict__ w,
    const float* __restrict__ bp, float* __restrict__ out)
{
    const int b = blockIdx.x, tid = threadIdx.x;
    __shared__ float rw[NL], cw[NL];
    if (tid < NL) { rw[tid] = g_rows[b * NL + tid]; cw[tid] = g_cols[b * NL + tid]; }
    __syncthreads();
    float nA0 = 0.f, nA1 = 0.f, nB0 = 0.f, nB1 = 0.f;
    for (int l = 0; l < NL; l++) {
        const float* r1 = E + (size_t)t1c[b * NL + l] * ND;
        const float* r2 = E + (size_t)t2c[b * NL + l] * ND;
        float wr = rw[l], wc = cw[l];
        nA0 += wr * r1[tid];  nA1 += wr * r1[tid + 256];
        nB0 += wc * r2[tid];  nB1 += wc * r2[tid + 256];
    }
    const float scale = g_inv_na[b] * g_inv_nb[b];
    float part = (nA0 * nB0 * w[tid] + nA1 * nB1 * w[tid + 256]) * scale;
    __shared__ float sh[8];
    #pragma unroll
    for (int o = 16; o; o >>= 1) part += __shfl_xor_sync(0xffffffffu, part, o);
    if ((tid & 31) == 0) sh[tid >> 5] = part;
    __syncthreads();
    if (tid < 8) {
        part = sh[tid];
        #pragma unroll
        for (int o = 4; o; o >>= 1) part += __shfl_xor_sync(0xffu, part, o);
        if (tid == 0) out[b] = part + bp[0];
    }
}

// ---------------------------------------------------------------------------
extern "C" void kernel_launch(void* const* d_in, const int* in_sizes, int n_in,
                              void* d_out, int out_size)
{
    (void)in_sizes; (void)n_in; (void)out_size;
    const int*   t1c = (const int*)d_in[2];
    const int*   t2c = (const int*)d_in[3];
    const float* E   = (const float*)d_in[4];
    const float* M   = (const float*)d_in[5];
    const float* w   = (const float*)d_in[6];
    const float* bp  = (const float*)d_in[7];
    float* out  = (float*)d_out;
    float* outS = out + NB;   // output = concat(logits[512], S[512*128*128])

    cudaFuncSetAttribute(gemm1_kernel, cudaFuncAttributeMaxDynamicSharedMemorySize, G1_SMEM);
    cudaFuncSetAttribute(gemm2_kernel, cudaFuncAttributeMaxDynamicSharedMemorySize, G2_SMEM);

    prep_mt_kernel<<<dim3(16, 16), 256>>>(M);
    prep_kernel<<<NB, 256>>>(t1c, t2c, E);
    gemm1_kernel<<<dim3(2, 512), 512, G1_SMEM>>>();
    gemm2_kernel<<<NB, 512, G2_SMEM>>>(outS);
    softmax_kernel<<<NB, 128>>>();
    final_kernel<<<NB, 256>>>(t1c, t2c, E, w, bp, out);
}

// round 11
// speedup vs baseline: 4.5404x; 1.5123x over previous
#include <cuda_runtime.h>
#include <cuda_fp16.h>
#include <math.h>
#include <stdint.h>

#define NB 512
#define NL 128
#define ND 512
#define NROWS ((size_t)NB * NL)   // 65536

// ---------------- scratch (static device globals) ----------------
// packed 2x fp16 per uint32; row = 256 uint32 = 512 cols = 1024 B
__device__ uint32_t g_A1h[NROWS * 256];   // gather(E,t1) fp16
__device__ uint32_t g_B2h[NROWS * 256];   // gather(E,t2) fp16
__device__ uint32_t g_Ch [NROWS * 256];   // C = A1 @ M, fp16
__device__ uint32_t g_Mth[ND * 256];      // Mt[n][k] fp16
__device__ float g_inv_na[NB], g_inv_nb[NB];
__device__ float g_rowm[NB * NL], g_colm[NB * NL];
__device__ float g_rows[NB * NL], g_cols[NB * NL];

// ---------------- helpers ----------------
__device__ __forceinline__ uint32_t smem_u32(const void* p) {
    uint32_t a;
    asm("{ .reg .u64 t; cvta.to.shared.u64 t, %1; cvt.u32.u64 %0, t; }" : "=r"(a) : "l"(p));
    return a;
}
__device__ __forceinline__ uint32_t swz(uint32_t o) { return o ^ ((o >> 3) & 0x70); }

#define CP16(dst, src) \
    asm volatile("cp.async.cg.shared.global [%0], [%1], 16;" :: "r"(dst), "l"(src))
#define CP_COMMIT() asm volatile("cp.async.commit_group;" ::: "memory")
#define CP_WAIT(n)  asm volatile("cp.async.wait_group %0;" :: "n"(n) : "memory")

__device__ __forceinline__ void ldm_x4(uint32_t* r, uint32_t addr) {
    asm volatile("ldmatrix.sync.aligned.m8n8.x4.shared.b16 {%0,%1,%2,%3}, [%4];"
        : "=r"(r[0]), "=r"(r[1]), "=r"(r[2]), "=r"(r[3]) : "r"(addr));
}
__device__ __forceinline__ void mma_f16(float* c, const uint32_t* a, const uint32_t* b) {
    asm volatile("mma.sync.aligned.m16n8k16.row.col.f32.f16.f16.f32 "
        "{%0,%1,%2,%3}, {%4,%5,%6,%7}, {%8,%9}, {%0,%1,%2,%3};"
        : "+f"(c[0]), "+f"(c[1]), "+f"(c[2]), "+f"(c[3])
        : "r"(a[0]), "r"(a[1]), "r"(a[2]), "r"(a[3]), "r"(b[0]), "r"(b[1]));
}
__device__ __forceinline__ uint32_t packh(float a, float b) {
    return ((uint32_t)__half_as_ushort(__float2half_rn(b)) << 16) |
           (uint32_t)__half_as_ushort(__float2half_rn(a));
}

// GEMM1 chunk: warp tile 32x64; A @ 0, B @ +16K (single fp16 product)
__device__ __forceinline__ void chunk_g1(uint32_t st, int lane, int m_base,
                                         int n_base, float acc[2][8][4]) {
    const int lrow = lane & 7, lmat = lane >> 3;
    const uint32_t a_row = (uint32_t)(m_base + (lmat & 1) * 8 + lrow) * 128;
    const uint32_t a_kb  = (uint32_t)((lmat >> 1) * 8) * 2;
    const uint32_t b_row = (uint32_t)(n_base + (lmat >> 1) * 8 + lrow) * 128;
    const uint32_t b_kb  = (uint32_t)((lmat & 1) * 8) * 2;
    #pragma unroll
    for (int ks = 0; ks < 4; ks++) {
        uint32_t Af[2][4];
        #pragma unroll
        for (int i = 0; i < 2; i++)
            ldm_x4(Af[i], st + swz(a_row + (uint32_t)i * 2048 + a_kb + ks * 32));
        #pragma unroll
        for (int j = 0; j < 4; j++) {
            uint32_t Bf[4];
            ldm_x4(Bf, st + 16384 + swz(b_row + (uint32_t)j * 2048 + b_kb + ks * 32));
            #pragma unroll
            for (int i = 0; i < 2; i++) {
                mma_f16(acc[i][2*j],   Af[i], &Bf[0]);
                mma_f16(acc[i][2*j+1], Af[i], &Bf[2]);
            }
        }
    }
}

// GEMM2 chunk: warp tile 32x32; C @ 0, B @ +16K (single fp16 product)
__device__ __forceinline__ void chunk_g2(uint32_t st, int lane, int m_base,
                                         int n_base, float acc[2][4][4]) {
    const int lrow = lane & 7, lmat = lane >> 3;
    const uint32_t a_row = (uint32_t)(m_base + (lmat & 1) * 8 + lrow) * 128;
    const uint32_t a_kb  = (uint32_t)((lmat >> 1) * 8) * 2;
    const uint32_t b_row = (uint32_t)(n_base + (lmat >> 1) * 8 + lrow) * 128;
    const uint32_t b_kb  = (uint32_t)((lmat & 1) * 8) * 2;
    #pragma unroll
    for (int ks = 0; ks < 4; ks++) {
        uint32_t Af[2][4];
        #pragma unroll
        for (int i = 0; i < 2; i++)
            ldm_x4(Af[i], st + swz(a_row + (uint32_t)i * 2048 + a_kb + ks * 32));
        #pragma unroll
        for (int j = 0; j < 2; j++) {
            uint32_t Bf[4];
            ldm_x4(Bf, st + 16384 + swz(b_row + (uint32_t)j * 2048 + b_kb + ks * 32));
            #pragma unroll
            for (int i = 0; i < 2; i++) {
                mma_f16(acc[i][2*j],   Af[i], &Bf[0]);
                mma_f16(acc[i][2*j+1], Af[i], &Bf[2]);
            }
        }
    }
}

// ---------------------------------------------------------------------------
// Kernel 0: transpose + fp16-pack att_mat -> g_Mth (Mt[n][k] = M[k][n])
// ---------------------------------------------------------------------------
__global__ __launch_bounds__(256) void prep_mt_kernel(const float* __restrict__ M) {
    __shared__ float t[32][33];
    const int n0 = blockIdx.x * 32, k0 = blockIdx.y * 32;
    const int tid = threadIdx.x;
    const int tx = tid & 31, ty = tid >> 5;
    #pragma unroll
    for (int j = 0; j < 32; j += 8)
        t[ty + j][tx] = M[(size_t)(k0 + ty + j) * ND + n0 + tx];
    __syncthreads();
    #pragma unroll
    for (int rep = 0; rep < 2; rep++) {
        int idx = rep * 256 + tid;
        int nl = idx >> 4, kp = idx & 15;
        g_Mth[(size_t)(n0 + nl) * 256 + (k0 >> 1) + kp] =
            packh(t[2 * kp][nl], t[2 * kp + 1][nl]);
    }
}

// ---------------------------------------------------------------------------
// Kernel 1: gather + fp16-pack + norms (fused)
// ---------------------------------------------------------------------------
__global__ __launch_bounds__(256) void prep_kernel(
    const int* __restrict__ t1c, const int* __restrict__ t2c,
    const float* __restrict__ E)
{
    const int b = blockIdx.x, tid = threadIdx.x;
    __shared__ int i1s[NL], i2s[NL];
    if (tid < NL) { i1s[tid] = t1c[b * NL + tid]; i2s[tid] = t2c[b * NL + tid]; }
    __syncthreads();
    float s1 = 0.f, s2 = 0.f;
    #pragma unroll 2
    for (int l = 0; l < NL; l++) {
        float2 v1 = ((const float2*)(E + (size_t)i1s[l] * ND))[tid];
        float2 v2 = ((const float2*)(E + (size_t)i2s[l] * ND))[tid];
        s1 += v1.x * v1.x + v1.y * v1.y;
        s2 += v2.x * v2.x + v2.y * v2.y;
        size_t o = (size_t)(b * NL + l) * 256 + tid;
        g_A1h[o] = packh(v1.x, v1.y);
        g_B2h[o] = packh(v2.x, v2.y);
    }
    __shared__ float sh1[8], sh2[8];
    #pragma unroll
    for (int o = 16; o; o >>= 1) {
        s1 += __shfl_xor_sync(0xffffffffu, s1, o);
        s2 += __shfl_xor_sync(0xffffffffu, s2, o);
    }
    if ((tid & 31) == 0) { sh1[tid >> 5] = s1; sh2[tid >> 5] = s2; }
    __syncthreads();
    if (tid < 8) {
        s1 = sh1[tid]; s2 = sh2[tid];
        #pragma unroll
        for (int o = 4; o; o >>= 1) {
            s1 += __shfl_xor_sync(0xffu, s1, o);
            s2 += __shfl_xor_sync(0xffu, s2, o);
        }
        if (tid == 0) { g_inv_na[b] = rsqrtf(s1); g_inv_nb[b] = rsqrtf(s2); }
    }
}

// ---------------------------------------------------------------------------
// Kernel 2: GEMM1 — C = A1 @ Mt^T (both fp16), 128x256 tile, 512 thr
//   stage: A 16K | B 32K = 48KB, 2 stages
// ---------------------------------------------------------------------------
#define G1_STAGE 49152
#define G1_SMEM  (2 * G1_STAGE + 1024)

__global__ __launch_bounds__(512, 1) void gemm1_kernel()
{
    extern __shared__ char smem_raw[];
    const uint32_t sb_raw = smem_u32(smem_raw);
    const uint32_t sb = (sb_raw + 1023) & ~1023u;
    const int tid = threadIdx.x;
    const int m0 = blockIdx.y * 128, n0 = blockIdx.x * 256;

    const char* srcA = (const char*)g_A1h + (size_t)m0 * 1024;
    const char* srcB = (const char*)g_Mth + (size_t)n0 * 1024;

    auto load_stage = [&](int c, int s) {
        const uint32_t stg = sb + s * G1_STAGE;
        #pragma unroll
        for (int q = 0; q < 2; q++) {     // A: 128 rows x 8 segs
            int sid = tid + q * 512;
            int r = sid >> 3, seg = sid & 7;
            uint32_t dst = stg + swz((uint32_t)(r * 128 + seg * 16));
            CP16(dst, srcA + (size_t)r * 1024 + c * 128 + seg * 16);
        }
        #pragma unroll
        for (int q = 0; q < 4; q++) {     // B: 256 rows x 8 segs
            int sid = tid + q * 512;
            int r = sid >> 3, seg = sid & 7;
            uint32_t dst = stg + 16384 + swz((uint32_t)(r * 128 + seg * 16));
            CP16(dst, srcB + (size_t)r * 1024 + c * 128 + seg * 16);
        }
    };

    float acc[2][8][4];
    #pragma unroll
    for (int i = 0; i < 2; i++)
        #pragma unroll
        for (int j = 0; j < 8; j++)
            #pragma unroll
            for (int q = 0; q < 4; q++) acc[i][j][q] = 0.f;

    load_stage(0, 0); CP_COMMIT();
    load_stage(1, 1); CP_COMMIT();
    CP_WAIT(1); __syncthreads();

    const int wid = tid >> 5, lane = tid & 31;
    const int m_base = (wid >> 2) * 32, n_base = (wid & 3) * 64;

    for (int c = 0; c < 8; c++) {
        chunk_g1(sb + (c & 1) * G1_STAGE, lane, m_base, n_base, acc);
        __syncthreads();
        if (c + 2 < 8) { load_stage(c + 2, c & 1); CP_COMMIT(); CP_WAIT(1); }
        else if (c == 6) { CP_WAIT(0); }
        __syncthreads();
    }

    // epilogue: fp16-pack acc -> g_Ch
    #pragma unroll
    for (int i = 0; i < 2; i++) {
        int gr = m0 + m_base + i * 16 + (lane >> 2);
        #pragma unroll
        for (int j8 = 0; j8 < 8; j8++) {
            int gc = n0 + n_base + j8 * 8 + (lane & 3) * 2;
            g_Ch[(size_t)gr * 256 + (gc >> 1)]       = packh(acc[i][j8][0], acc[i][j8][1]);
            g_Ch[(size_t)(gr + 8) * 256 + (gc >> 1)] = packh(acc[i][j8][2], acc[i][j8][3]);
        }
    }
}

// ---------------------------------------------------------------------------
// Kernel 3: GEMM2 — S[b] = tanh(scale * C[b] @ B2[b]^T), fused means
//   512 thr, 16 warps (4x4), warp tile 32x32; stage C 16K | B 16K = 32KB x 3
// ---------------------------------------------------------------------------
#define G2_STAGE 32768
#define G2_SMEM  (3 * G2_STAGE + 1024)

__global__ __launch_bounds__(512, 1) void gemm2_kernel(float* __restrict__ outS)
{
    extern __shared__ char smem_raw[];
    const uint32_t sb_raw = smem_u32(smem_raw);
    const uint32_t sb = (sb_raw + 1023) & ~1023u;
    char* smem = smem_raw + (sb - sb_raw);
    const int tid = threadIdx.x;
    const int b = blockIdx.x;

    const char* srcC = (const char*)g_Ch  + (size_t)b * NL * 1024;
    const char* srcB = (const char*)g_B2h + (size_t)b * NL * 1024;

    auto load_stage = [&](int c, int s) {
        const uint32_t stg = sb + s * G2_STAGE;
        #pragma unroll
        for (int q = 0; q < 2; q++) {
            int sid = tid + q * 512;
            int r = sid >> 3, seg = sid & 7;
            uint32_t dst = stg + swz((uint32_t)(r * 128 + seg * 16));
            size_t so = (size_t)r * 1024 + c * 128 + seg * 16;
            CP16(dst, srcC + so);
            CP16(dst + 16384, srcB + so);
        }
    };

    float acc[2][4][4];
    #pragma unroll
    for (int i = 0; i < 2; i++)
        #pragma unroll
        for (int j = 0; j < 4; j++)
            #pragma unroll
            for (int q = 0; q < 4; q++) acc[i][j][q] = 0.f;

    load_stage(0, 0); CP_COMMIT();
    load_stage(1, 1); CP_COMMIT();
    load_stage(2, 2); CP_COMMIT();
    CP_WAIT(2); __syncthreads();

    const int wid = tid >> 5, lane = tid & 31;
    const int m_base = (wid >> 2) * 32, n_base = (wid & 3) * 32;

    for (int c = 0; c < 8; c++) {
        chunk_g2(sb + (c % 3) * G2_STAGE, lane, m_base, n_base, acc);
        __syncthreads();
        if (c + 3 < 8)      { load_stage(c + 3, c % 3); CP_COMMIT(); CP_WAIT(2); }
        else if (c == 5)    { CP_WAIT(1); }
        else if (c == 6)    { CP_WAIT(0); }
        __syncthreads();
    }

    // epilogue: tanh + S store + fused row/col means
    float* rs = (float*)smem;
    float* cs = rs + 128;
    if (tid < 128) { rs[tid] = 0.f; cs[tid] = 0.f; }
    __syncthreads();

    const float scale = g_inv_na[b] * g_inv_nb[b];
    float* Sb = outS + (size_t)b * NL * NL;
    float cpart0[4], cpart1[4];
    #pragma unroll
    for (int j8 = 0; j8 < 4; j8++) { cpart0[j8] = 0.f; cpart1[j8] = 0.f; }
    float rpart[2][2] = {{0.f, 0.f}, {0.f, 0.f}};

    #pragma unroll
    for (int i = 0; i < 2; i++) {
        int r0 = m_base + i * 16 + (lane >> 2);
        #pragma unroll
        for (int j8 = 0; j8 < 4; j8++) {
            int col = n_base + j8 * 8 + (lane & 3) * 2;
            float v0 = tanhf(acc[i][j8][0] * scale);
            float v1 = tanhf(acc[i][j8][1] * scale);
            float v2 = tanhf(acc[i][j8][2] * scale);
            float v3 = tanhf(acc[i][j8][3] * scale);
            float* p = Sb + (size_t)r0 * NL + col;
            *(float2*)p = make_float2(v0, v1);
            *(float2*)(p + 8 * NL) = make_float2(v2, v3);
            rpart[i][0] += v0 + v1;
            rpart[i][1] += v2 + v3;
            cpart0[j8] += v0 + v2;
            cpart1[j8] += v1 + v3;
        }
    }
    #pragma unroll
    for (int i = 0; i < 2; i++) {
        atomicAdd(&rs[m_base + i * 16 + (lane >> 2)], rpart[i][0]);
        atomicAdd(&rs[m_base + i * 16 + (lane >> 2) + 8], rpart[i][1]);
    }
    #pragma unroll
    for (int j8 = 0; j8 < 4; j8++) {
        atomicAdd(&cs[n_base + j8 * 8 + (lane & 3) * 2], cpart0[j8]);
        atomicAdd(&cs[n_base + j8 * 8 + (lane & 3) * 2 + 1], cpart1[j8]);
    }
    __syncthreads();
    if (tid < 128) {
        g_rowm[b * NL + tid] = rs[tid] * (1.0f / NL);
        g_colm[b * NL + tid] = cs[tid] * (1.0f / NL);
    }
}

// ---------------------------------------------------------------------------
// Kernel 4: softmax over precomputed means (tiny)
// ---------------------------------------------------------------------------
__global__ __launch_bounds__(128) void softmax_kernel()
{
    const int b = blockIdx.x, t = threadIdx.x;
    __shared__ float buf[128];
    float v = g_rowm[b * NL + t];
    buf[t] = v; __syncthreads();
    for (int s = 64; s; s >>= 1) { if (t < s) buf[t] = fmaxf(buf[t], buf[t + s]); __syncthreads(); }
    float mx = buf[0]; __syncthreads();
    float e = expf(v - mx);
    buf[t] = e; __syncthreads();
    for (int s = 64; s; s >>= 1) { if (t < s) buf[t] += buf[t + s]; __syncthreads(); }
    g_rows[b * NL + t] = e / buf[0];
    __syncthreads();
    v = g_colm[b * NL + t];
    buf[t] = v; __syncthreads();
    for (int s = 64; s; s >>= 1) { if (t < s) buf[t] = fmaxf(buf[t], buf[t + s]); __syncthreads(); }
    mx = buf[0]; __syncthreads();
    e = expf(v - mx);
    buf[t] = e; __syncthreads();
    for (int s = 64; s; s >>= 1) { if (t < s) buf[t] += buf[t + s]; __syncthreads(); }
    g_cols[b * NL + t] = e / buf[0];
}

// ---------------------------------------------------------------------------
// Kernel 5: weighted reduce from fp16 arrays (sequential reads)
// ---------------------------------------------------------------------------
__global__ __launch_bounds__(256) void final_kernel(
    const float* __restrict__ w, const float* __restrict__ bp,
    float* __restrict__ out)
{
    const int b = blockIdx.x, tid = threadIdx.x;
    __shared__ float rw[NL], cw[NL];
    if (tid < NL) { rw[tid] = g_rows[b * NL + tid]; cw[tid] = g_cols[b * NL + tid]; }
    __syncthreads();
    float ax = 0.f, ay = 0.f, bx = 0.f, by = 0.f;
    #pragma unroll 4
    for (int l = 0; l < NL; l++) {
        size_t o = (size_t)(b * NL + l) * 256 + tid;
        uint32_t av = g_A1h[o], bv = g_B2h[o];
        __half2 ah = *reinterpret_cast<__half2*>(&av);
        __half2 bh = *reinterpret_cast<__half2*>(&bv);
        float wr = rw[l], wc = cw[l];
        ax += wr * __half2float(ah.x);  ay += wr * __half2float(ah.y);
        bx += wc * __half2float(bh.x);  by += wc * __half2float(bh.y);
    }
    float2 wv = ((const float2*)w)[tid];
    float part = (ax * bx * wv.x + ay * by * wv.y) * (g_inv_na[b] * g_inv_nb[b]);
    __shared__ float sh[8];
    #pragma unroll
    for (int o = 16; o; o >>= 1) part += __shfl_xor_sync(0xffffffffu, part, o);
    if ((tid & 31) == 0) sh[tid >> 5] = part;
    __syncthreads();
    if (tid < 8) {
        part = sh[tid];
        #pragma unroll
        for (int o = 4; o; o >>= 1) part += __shfl_xor_sync(0xffu, part, o);
        if (tid == 0) out[b] = part + bp[0];
    }
}

// ---------------------------------------------------------------------------
extern "C" void kernel_launch(void* const* d_in, const int* in_sizes, int n_in,
                              void* d_out, int out_size)
{
    (void)in_sizes; (void)n_in; (void)out_size;
    const int*   t1c = (const int*)d_in[2];
    const int*   t2c = (const int*)d_in[3];
    const float* E   = (const float*)d_in[4];
    const float* M   = (const float*)d_in[5];
    const float* w   = (const float*)d_in[6];
    const float* bp  = (const float*)d_in[7];
    float* out  = (float*)d_out;
    float* outS = out + NB;   // output = concat(logits[512], S[512*128*128])

    cudaFuncSetAttribute(gemm1_kernel, cudaFuncAttributeMaxDynamicSharedMemorySize, G1_SMEM);
    cudaFuncSetAttribute(gemm2_kernel, cudaFuncAttributeMaxDynamicSharedMemorySize, G2_SMEM);

    prep_mt_kernel<<<dim3(16, 16), 256>>>(M);
    prep_kernel<<<NB, 256>>>(t1c, t2c, E);
    gemm1_kernel<<<dim3(2, 512), 512, G1_SMEM>>>();
    gemm2_kernel<<<NB, 512, G2_SMEM>>>(outS);
    softmax_kernel<<<NB, 128>>>();
    final_kernel<<<NB, 256>>>(w, bp, out);
}